// round 1
// baseline (speedup 1.0000x reference)
#include <cuda_runtime.h>
#include <cstdint>
#include <cstddef>

// Problem dims (fixed by the dataset)
#define Bn   1024
#define Nn   64
#define Fn   1024
#define H1n  256
#define H2n  128
#define NCn  128
#define Mn   (Bn*Nn)      // 65536
#define ALPHA_LRELU 0.2f
#define BN_EPS 1e-5f

// ---------------------------------------------------------------------------
// Scratch (static device globals — allocation-free, per harness rules)
// ---------------------------------------------------------------------------
__device__ float g_nbh1[(size_t)Mn * H1n];   // 64 MB
__device__ float g_xh1 [Bn * H1n];
__device__ float g_x1  [Bn * H1n];
__device__ float g_mb1 [Bn];
__device__ float g_rb1 [Bn];
__device__ float g_px1 [Bn];
__device__ float g_pxq1[Bn];
__device__ float g_bn1 [2];
__device__ float g_nbh2[(size_t)Mn * H2n];   // 32 MB
__device__ float g_xh2 [Bn * H2n];
__device__ float g_x2  [Bn * H2n];
__device__ float g_px2 [Bn];
__device__ float g_pxq2[Bn];
__device__ float g_bn2 [2];

// ---------------------------------------------------------------------------
// Generic tiled GEMM:  C[m,n] = op(A[m,:]) . Bmat[n,:] + bias[n]
//   A is [M,K] row-major, Bmat is [Ntot,K] row-major (i.e. we compute A @ B^T)
//   mode 0: op(v) = sign(v)  (the l2norm-over-singleton-channel trick)
//   mode 1: op(v) = relu(g*(v - mean[row/statdiv]) * rstd[row/statdiv] + be)
// Tile: 128x128x16, 256 threads, 8x8 per-thread register tile.
// ---------------------------------------------------------------------------
__global__ __launch_bounds__(256, 2)
void gemm_k(const float* __restrict__ A, const float* __restrict__ Bm,
            const float* __restrict__ bias, float* __restrict__ C,
            int M, int Ntot, int K, int mode,
            const float* __restrict__ meanp, const float* __restrict__ rstdp,
            int statdiv, const float* __restrict__ gptr,
            const float* __restrict__ beptr)
{
    __shared__ float As[16][132];
    __shared__ float Bs[16][132];

    const int tid = threadIdx.x;
    const int m0 = blockIdx.x * 128;
    const int n0 = blockIdx.y * 128;

    const int lr = tid >> 1;          // 0..127  : row within tile this thread loads
    const int lc = (tid & 1) * 8;     // 0 or 8  : k-offset this thread loads

    const float* pA = A  + (size_t)(m0 + lr) * K + lc;
    const float* pB = Bm + (size_t)(n0 + lr) * K + lc;

    float rm = 0.f, rr = 0.f, gg = 0.f, bb = 0.f;
    if (mode == 1) {
        const int si = (m0 + lr) / statdiv;
        rm = meanp[si]; rr = rstdp[si];
        gg = *gptr;     bb = *beptr;
    }

    float acc[8][8];
#pragma unroll
    for (int i = 0; i < 8; i++)
#pragma unroll
        for (int j = 0; j < 8; j++) acc[i][j] = 0.f;

    const int ty = tid >> 4;   // 0..15 -> row group
    const int tx = tid & 15;   // 0..15 -> col group

    for (int k0 = 0; k0 < K; k0 += 16) {
        float4 a0 = *(const float4*)(pA + k0);
        float4 a1 = *(const float4*)(pA + k0 + 4);
        float4 b0 = *(const float4*)(pB + k0);
        float4 b1 = *(const float4*)(pB + k0 + 4);

        float av[8] = {a0.x, a0.y, a0.z, a0.w, a1.x, a1.y, a1.z, a1.w};
#pragma unroll
        for (int j = 0; j < 8; j++) {
            float v = av[j];
            if (mode == 0) {
                float afv = fabsf(v);
                v = (afv >= 1e-12f) ? copysignf(1.f, v) : v * 1e12f;
            } else {
                v = fmaxf(gg * (v - rm) * rr + bb, 0.f);
            }
            As[lc + j][lr] = v;
        }
        float bv[8] = {b0.x, b0.y, b0.z, b0.w, b1.x, b1.y, b1.z, b1.w};
#pragma unroll
        for (int j = 0; j < 8; j++) Bs[lc + j][lr] = bv[j];

        __syncthreads();

#pragma unroll
        for (int kk = 0; kk < 16; kk++) {
            float a[8], b[8];
#pragma unroll
            for (int i = 0; i < 8; i++) a[i] = As[kk][ty * 8 + i];
#pragma unroll
            for (int j = 0; j < 8; j++) b[j] = Bs[kk][tx * 8 + j];
#pragma unroll
            for (int i = 0; i < 8; i++)
#pragma unroll
                for (int j = 0; j < 8; j++) acc[i][j] += a[i] * b[j];
        }
        __syncthreads();
    }

    float bs[8];
#pragma unroll
    for (int j = 0; j < 8; j++) bs[j] = bias[n0 + tx * 8 + j];
#pragma unroll
    for (int i = 0; i < 8; i++) {
        float* cp = C + (size_t)(m0 + ty * 8 + i) * Ntot + n0 + tx * 8;
        float4 o0 = make_float4(acc[i][0] + bs[0], acc[i][1] + bs[1],
                                acc[i][2] + bs[2], acc[i][3] + bs[3]);
        float4 o1 = make_float4(acc[i][4] + bs[4], acc[i][5] + bs[5],
                                acc[i][6] + bs[6], acc[i][7] + bs[7]);
        *(float4*)cp       = o0;
        *(float4*)(cp + 4) = o1;
    }
}

// ---------------------------------------------------------------------------
// Attention layer 1 (H=256). One block per graph node b, 256 threads.
// Computes: scores -> leakyrelu -> softmax over N -> x1[b,:] = sum_n A*nbh1
// Plus per-b stats of nbh1 (for neighbor BN) and per-b partial sums of x1
// (for the global x BN).
// ---------------------------------------------------------------------------
__global__ void attn1_k(const float* __restrict__ nbh, const float* __restrict__ xh,
                        const float* __restrict__ a_self, const float* __restrict__ a_nb,
                        float* __restrict__ x1, float* __restrict__ mb,
                        float* __restrict__ rb, float* __restrict__ px,
                        float* __restrict__ pxq)
{
    const int b = blockIdx.x, tid = threadIdx.x;
    __shared__ float red[256];
    __shared__ float sc[64];

    const float* base = nbh + (size_t)b * Nn * H1n;

    // self score: dot(xh1[b,:], a_self)
    red[tid] = xh[b * H1n + tid] * a_self[tid];
    __syncthreads();
    for (int s = 128; s > 0; s >>= 1) {
        if (tid < s) red[tid] += red[tid + s];
        __syncthreads();
    }
    const float sx = red[0];
    __syncthreads();

    // neighbor scores: warp w handles 8 n's
    const int w = tid >> 5, l = tid & 31;
#pragma unroll
    for (int nn = 0; nn < 8; nn++) {
        const int n = w * 8 + nn;
        const float* row = base + n * H1n;
        float acc = 0.f;
#pragma unroll
        for (int j = 0; j < 8; j++) acc += row[l + 32 * j] * a_nb[l + 32 * j];
#pragma unroll
        for (int o = 16; o > 0; o >>= 1) acc += __shfl_down_sync(0xffffffffu, acc, o);
        if (l == 0) sc[n] = sx + acc;
    }
    __syncthreads();

    // leakyrelu + softmax over the 64 neighbors (warp 0)
    if (w == 0) {
        float v0 = sc[l], v1 = sc[l + 32];
        v0 = v0 > 0.f ? v0 : ALPHA_LRELU * v0;
        v1 = v1 > 0.f ? v1 : ALPHA_LRELU * v1;
        float mx = fmaxf(v0, v1);
#pragma unroll
        for (int o = 16; o > 0; o >>= 1) mx = fmaxf(mx, __shfl_xor_sync(0xffffffffu, mx, o));
        float e0 = __expf(v0 - mx), e1 = __expf(v1 - mx);
        float s = e0 + e1;
#pragma unroll
        for (int o = 16; o > 0; o >>= 1) s += __shfl_xor_sync(0xffffffffu, s, o);
        const float inv = 1.f / s;
        sc[l] = e0 * inv; sc[l + 32] = e1 * inv;
    }
    __syncthreads();

    // weighted sum + neighbor stats (thread = h)
    float acc = 0.f, sm = 0.f, sq = 0.f;
#pragma unroll 8
    for (int n = 0; n < Nn; n++) {
        const float v = base[n * H1n + tid];
        acc += sc[n] * v;
        sm += v;
        sq += v * v;
    }
    x1[b * H1n + tid] = acc;

    // reduce neighbor sum
    red[tid] = sm; __syncthreads();
    for (int s = 128; s > 0; s >>= 1) { if (tid < s) red[tid] += red[tid + s]; __syncthreads(); }
    const float S = red[0]; __syncthreads();
    // reduce neighbor sumsq
    red[tid] = sq; __syncthreads();
    for (int s = 128; s > 0; s >>= 1) { if (tid < s) red[tid] += red[tid + s]; __syncthreads(); }
    const float SQ = red[0]; __syncthreads();
    // reduce x1 partials
    red[tid] = acc; __syncthreads();
    for (int s = 128; s > 0; s >>= 1) { if (tid < s) red[tid] += red[tid + s]; __syncthreads(); }
    const float SX = red[0]; __syncthreads();
    red[tid] = acc * acc; __syncthreads();
    for (int s = 128; s > 0; s >>= 1) { if (tid < s) red[tid] += red[tid + s]; __syncthreads(); }
    const float SXQ = red[0];

    if (tid == 0) {
        const float inv_cnt = 1.f / (float)(Nn * H1n);
        const float mean = S * inv_cnt;
        const float var  = SQ * inv_cnt - mean * mean;
        mb[b] = mean;
        rb[b] = rsqrtf(fmaxf(var, 0.f) + BN_EPS);
        px[b]  = SX;
        pxq[b] = SXQ;
    }
}

// ---------------------------------------------------------------------------
// Attention layer 2 (H=128). One block per node, 128 threads.
// ---------------------------------------------------------------------------
__global__ void attn2_k(const float* __restrict__ nbh, const float* __restrict__ xh,
                        const float* __restrict__ a_self, const float* __restrict__ a_nb,
                        float* __restrict__ x2, float* __restrict__ px,
                        float* __restrict__ pxq)
{
    const int b = blockIdx.x, tid = threadIdx.x;
    __shared__ float red[128];
    __shared__ float sc[64];

    const float* base = nbh + (size_t)b * Nn * H2n;

    red[tid] = xh[b * H2n + tid] * a_self[tid];
    __syncthreads();
    for (int s = 64; s > 0; s >>= 1) { if (tid < s) red[tid] += red[tid + s]; __syncthreads(); }
    const float sx = red[0];
    __syncthreads();

    const int w = tid >> 5, l = tid & 31;   // 4 warps, 16 n each
#pragma unroll
    for (int nn = 0; nn < 16; nn++) {
        const int n = w * 16 + nn;
        const float* row = base + n * H2n;
        float acc = 0.f;
#pragma unroll
        for (int j = 0; j < 4; j++) acc += row[l + 32 * j] * a_nb[l + 32 * j];
#pragma unroll
        for (int o = 16; o > 0; o >>= 1) acc += __shfl_down_sync(0xffffffffu, acc, o);
        if (l == 0) sc[n] = sx + acc;
    }
    __syncthreads();

    if (w == 0) {
        float v0 = sc[l], v1 = sc[l + 32];
        v0 = v0 > 0.f ? v0 : ALPHA_LRELU * v0;
        v1 = v1 > 0.f ? v1 : ALPHA_LRELU * v1;
        float mx = fmaxf(v0, v1);
#pragma unroll
        for (int o = 16; o > 0; o >>= 1) mx = fmaxf(mx, __shfl_xor_sync(0xffffffffu, mx, o));
        float e0 = __expf(v0 - mx), e1 = __expf(v1 - mx);
        float s = e0 + e1;
#pragma unroll
        for (int o = 16; o > 0; o >>= 1) s += __shfl_xor_sync(0xffffffffu, s, o);
        const float inv = 1.f / s;
        sc[l] = e0 * inv; sc[l + 32] = e1 * inv;
    }
    __syncthreads();

    float acc = 0.f;
#pragma unroll 8
    for (int n = 0; n < Nn; n++) acc += sc[n] * base[n * H2n + tid];
    x2[b * H2n + tid] = acc;

    red[tid] = acc; __syncthreads();
    for (int s = 64; s > 0; s >>= 1) { if (tid < s) red[tid] += red[tid + s]; __syncthreads(); }
    const float SX = red[0]; __syncthreads();
    red[tid] = acc * acc; __syncthreads();
    for (int s = 64; s > 0; s >>= 1) { if (tid < s) red[tid] += red[tid + s]; __syncthreads(); }
    const float SXQ = red[0];

    if (tid == 0) { px[b] = SX; pxq[b] = SXQ; }
}

// ---------------------------------------------------------------------------
// Finalize global BN stats from per-block partials (1 block, 1024 threads).
// ---------------------------------------------------------------------------
__global__ void bnstats_k(const float* __restrict__ px, const float* __restrict__ pxq,
                          float* __restrict__ bn, float invcnt)
{
    __shared__ float r1[1024];
    __shared__ float r2[1024];
    const int t = threadIdx.x;
    r1[t] = px[t]; r2[t] = pxq[t];
    __syncthreads();
    for (int s = 512; s > 0; s >>= 1) {
        if (t < s) { r1[t] += r1[t + s]; r2[t] += r2[t + s]; }
        __syncthreads();
    }
    if (t == 0) {
        const float mean = r1[0] * invcnt;
        const float var  = r2[0] * invcnt - mean * mean;
        bn[0] = mean;
        bn[1] = rsqrtf(fmaxf(var, 0.f) + BN_EPS);
    }
}

// ---------------------------------------------------------------------------
// Final: BN-ReLU x2 + logits = x2n @ Wl^T + bl. One block per b, 128 threads.
// ---------------------------------------------------------------------------
__global__ void logits_k(const float* __restrict__ x2, const float* __restrict__ bn2,
                         const float* __restrict__ gptr, const float* __restrict__ beptr,
                         const float* __restrict__ Wl, const float* __restrict__ bl,
                         float* __restrict__ out)
{
    const int b = blockIdx.x, t = threadIdx.x;
    __shared__ float xn[H2n];
    const float m = bn2[0], r = bn2[1], g = gptr[0], be = beptr[0];
    float v = x2[b * H2n + t];
    xn[t] = fmaxf(g * (v - m) * r + be, 0.f);
    __syncthreads();

    const float* wr = Wl + t * H2n;
    float acc = bl[t];
#pragma unroll 8
    for (int h = 0; h < H2n; h++) acc += xn[h] * wr[h];
    out[b * NCn + t] = acc;
}

// ---------------------------------------------------------------------------
// Launch
// ---------------------------------------------------------------------------
extern "C" void kernel_launch(void* const* d_in, const int* in_sizes, int n_in,
                              void* d_out, int out_size)
{
    (void)in_sizes; (void)n_in; (void)out_size;
    const float* x   = (const float*)d_in[0];
    const float* nb  = (const float*)d_in[1];
    const float* W1  = (const float*)d_in[2];
    const float* b1  = (const float*)d_in[3];
    const float* a11 = (const float*)d_in[4];
    const float* a12 = (const float*)d_in[5];
    const float* g1  = (const float*)d_in[6];
    const float* be1 = (const float*)d_in[7];
    const float* W2  = (const float*)d_in[8];
    const float* b2  = (const float*)d_in[9];
    const float* a21 = (const float*)d_in[10];
    const float* a22 = (const float*)d_in[11];
    const float* g2  = (const float*)d_in[12];
    const float* be2 = (const float*)d_in[13];
    const float* Wl  = (const float*)d_in[14];
    const float* bl  = (const float*)d_in[15];
    float* out = (float*)d_out;

    float *nbh1, *xh1, *x1, *mb1, *rb1, *px1, *pxq1, *bn1;
    float *nbh2, *xh2, *x2, *px2, *pxq2, *bn2;
    cudaGetSymbolAddress((void**)&nbh1, g_nbh1);
    cudaGetSymbolAddress((void**)&xh1,  g_xh1);
    cudaGetSymbolAddress((void**)&x1,   g_x1);
    cudaGetSymbolAddress((void**)&mb1,  g_mb1);
    cudaGetSymbolAddress((void**)&rb1,  g_rb1);
    cudaGetSymbolAddress((void**)&px1,  g_px1);
    cudaGetSymbolAddress((void**)&pxq1, g_pxq1);
    cudaGetSymbolAddress((void**)&bn1,  g_bn1);
    cudaGetSymbolAddress((void**)&nbh2, g_nbh2);
    cudaGetSymbolAddress((void**)&xh2,  g_xh2);
    cudaGetSymbolAddress((void**)&x2,   g_x2);
    cudaGetSymbolAddress((void**)&px2,  g_px2);
    cudaGetSymbolAddress((void**)&pxq2, g_pxq2);
    cudaGetSymbolAddress((void**)&bn2,  g_bn2);

    // Layer 1 GEMMs: sign(input) @ W1^T + b1
    gemm_k<<<dim3(Mn / 128, H1n / 128), 256>>>(nb, W1, b1, nbh1, Mn, H1n, Fn, 0,
                                               nullptr, nullptr, 1, nullptr, nullptr);
    gemm_k<<<dim3(Bn / 128, H1n / 128), 256>>>(x, W1, b1, xh1, Bn, H1n, Fn, 0,
                                               nullptr, nullptr, 1, nullptr, nullptr);
    // Attention 1 + per-node neighbor BN stats + x1 partial stats
    attn1_k<<<Bn, 256>>>(nbh1, xh1, a11, a12, x1, mb1, rb1, px1, pxq1);
    bnstats_k<<<1, 1024>>>(px1, pxq1, bn1, 1.f / (float)(Bn * H1n));

    // Layer 2 GEMMs: BN-ReLU(input) @ W2^T + b2
    gemm_k<<<dim3(Mn / 128, H2n / 128), 256>>>(nbh1, W2, b2, nbh2, Mn, H2n, H1n, 1,
                                               mb1, rb1, Nn, g1, be1);
    gemm_k<<<dim3(Bn / 128, H2n / 128), 256>>>(x1, W2, b2, xh2, Bn, H2n, H1n, 1,
                                               bn1, bn1 + 1, 1 << 30, g1, be1);
    // Attention 2 + x2 partial stats
    attn2_k<<<Bn, 128>>>(nbh2, xh2, a21, a22, x2, px2, pxq2);
    bnstats_k<<<1, 1024>>>(px2, pxq2, bn2, 1.f / (float)(Bn * H2n));

    // BN-ReLU + classifier
    logits_k<<<Bn, 128>>>(x2, bn2, g2, be2, Wl, bl, out);
}

// round 3
// speedup vs baseline: 1.7340x; 1.7340x over previous
#include <cuda_runtime.h>
#include <cuda_bf16.h>
#include <cstdint>
#include <cstddef>

// Problem dims (fixed by the dataset)
#define Bn   1024
#define Nn   64
#define Fn   1024
#define H1n  256
#define H2n  128
#define NCn  128
#define Mn   (Bn*Nn)      // 65536
#define ALPHA_LRELU 0.2f
#define BN_EPS 1e-5f

// ---------------------------------------------------------------------------
// Scratch (static device globals — allocation-free, per harness rules)
// ---------------------------------------------------------------------------
__device__ float g_nbh1[(size_t)Mn * H1n];   // 64 MB
__device__ float g_xh1 [Bn * H1n];
__device__ float g_x1  [Bn * H1n];
__device__ float g_mb1 [Bn];
__device__ float g_rb1 [Bn];
__device__ float g_px1 [Bn];
__device__ float g_pxq1[Bn];
__device__ float g_bn1 [2];
__device__ float g_nbh2[(size_t)Mn * H2n];   // 32 MB
__device__ float g_xh2 [Bn * H2n];
__device__ float g_x2  [Bn * H2n];
__device__ float g_px2 [Bn];
__device__ float g_pxq2[Bn];
__device__ float g_bn2 [2];
__device__ __nv_bfloat16 g_w1hi[H1n * Fn];   // 512 KB
__device__ __nv_bfloat16 g_w1lo[H1n * Fn];   // 512 KB

// ---------------------------------------------------------------------------
// PTX helpers: ldmatrix + mma.sync (arch-stable, no sm_103a-only features)
// ---------------------------------------------------------------------------
__device__ __forceinline__ uint32_t smem_u32(const void* p) {
    uint32_t a;
    asm("{ .reg .u64 t; cvta.to.shared.u64 t, %1; cvt.u32.u64 %0, t; }" : "=r"(a) : "l"(p));
    return a;
}
__device__ __forceinline__ void ldsm_x4(uint32_t* r, uint32_t addr) {
    asm volatile("ldmatrix.sync.aligned.m8n8.x4.shared.b16 {%0,%1,%2,%3}, [%4];"
                 : "=r"(r[0]), "=r"(r[1]), "=r"(r[2]), "=r"(r[3]) : "r"(addr));
}
__device__ __forceinline__ void mma16816(float* c, const uint32_t* a, const uint32_t* b) {
    asm volatile("mma.sync.aligned.m16n8k16.row.col.f32.bf16.bf16.f32 "
                 "{%0,%1,%2,%3}, {%4,%5,%6,%7}, {%8,%9}, {%0,%1,%2,%3};"
                 : "+f"(c[0]), "+f"(c[1]), "+f"(c[2]), "+f"(c[3])
                 : "r"(a[0]), "r"(a[1]), "r"(a[2]), "r"(a[3]), "r"(b[0]), "r"(b[1]));
}
__device__ __forceinline__ uint32_t swz128(uint32_t off) { return off ^ ((off >> 3) & 0x70); }

__device__ __forceinline__ uint32_t pack_sign_bf16x2(float a, float b) {
    float sa = (fabsf(a) >= 1e-12f) ? copysignf(1.f, a) : a * 1e12f;
    float sb = (fabsf(b) >= 1e-12f) ? copysignf(1.f, b) : b * 1e12f;
    __nv_bfloat162 h = __floats2bfloat162_rn(sa, sb);   // .x = low 16 bits
    return *reinterpret_cast<uint32_t*>(&h);
}

// ---------------------------------------------------------------------------
// W1 split: Whi = bf16(W), Wlo = bf16(W - Whi)
// ---------------------------------------------------------------------------
__global__ void wsplit_k(const float* __restrict__ W, __nv_bfloat16* __restrict__ hi,
                         __nv_bfloat16* __restrict__ lo, int n)
{
    int i = blockIdx.x * blockDim.x + threadIdx.x;
    if (i < n) {
        float w = W[i];
        __nv_bfloat16 h = __float2bfloat16_rn(w);
        hi[i] = h;
        lo[i] = __float2bfloat16_rn(w - __bfloat162float(h));
    }
}

// ---------------------------------------------------------------------------
// mma.sync GEMM1: C[M,256] = sign(A[M,1024]) @ W1^T + b1, split-bf16 (hi+lo
// into one fp32 accumulator). CTA tile 128x128, K-chunk 64, 8 warps (32x64
// warp tile). SW128-swizzled SMEM, ldmatrix.x4 fragment loads.
// ---------------------------------------------------------------------------
__global__ __launch_bounds__(256, 2)
void tc_gemm1_k(const float* __restrict__ A, const __nv_bfloat16* __restrict__ Whi,
                const __nv_bfloat16* __restrict__ Wlo, const float* __restrict__ bias,
                float* __restrict__ C, int K, int Ntot)
{
    __shared__ char smem[49152];   // A: 16KB | Bhi: 16KB | Blo: 16KB
    const uint32_t sb = smem_u32(smem);
    const uint32_t aB = sb, bhB = sb + 16384, blB = sb + 32768;

    const int tid = threadIdx.x;
    const int wid = tid >> 5, lane = tid & 31;
    const int m0 = blockIdx.x * 128;
    const int n0 = blockIdx.y * 128;

    const int mrow0 = (wid >> 1) * 32;   // warp m-offset in tile
    const int ncol0 = (wid & 1) * 64;    // warp n-offset in tile

    // producers: 2 threads per row, 32 elements each
    const int r  = tid >> 1;
    const int c0 = (tid & 1) * 32;
    const float* aSrc = A + (size_t)(m0 + r) * K + c0;
    const __nv_bfloat16* hSrc = Whi + (size_t)(n0 + r) * K + c0;
    const __nv_bfloat16* lSrc = Wlo + (size_t)(n0 + r) * K + c0;

    float acc[2][8][4];
#pragma unroll
    for (int i = 0; i < 2; i++)
#pragma unroll
        for (int g = 0; g < 8; g++)
#pragma unroll
            for (int q = 0; q < 4; q++) acc[i][g][q] = 0.f;

    // per-thread ldmatrix smem offsets (row part; k part added per step)
    const int aRow[2] = { mrow0 + 0 * 16 + (lane & 15), mrow0 + 1 * 16 + (lane & 15) };
    const int aKof   = (lane >> 4) << 3;
    const int bRowBase = ncol0 + (lane & 7) + ((lane >> 4) << 3);
    const int bKof   = ((lane >> 3) & 1) << 3;

    for (int k0 = 0; k0 < K; k0 += 64) {
        // ---- producers ----
#pragma unroll
        for (int j = 0; j < 4; j++) {
            float4 f0 = *(const float4*)(aSrc + k0 + j * 8);
            float4 f1 = *(const float4*)(aSrc + k0 + j * 8 + 4);
            uint4 o;
            o.x = pack_sign_bf16x2(f0.x, f0.y);
            o.y = pack_sign_bf16x2(f0.z, f0.w);
            o.z = pack_sign_bf16x2(f1.x, f1.y);
            o.w = pack_sign_bf16x2(f1.z, f1.w);
            *(uint4*)(smem + swz128((uint32_t)(r * 128 + (c0 + j * 8) * 2))) = o;
            uint4 vh = *(const uint4*)(hSrc + k0 + j * 8);
            uint4 vl = *(const uint4*)(lSrc + k0 + j * 8);
            uint32_t so = swz128((uint32_t)(r * 128 + (c0 + j * 8) * 2));
            *(uint4*)(smem + 16384 + so) = vh;
            *(uint4*)(smem + 32768 + so) = vl;
        }
        __syncthreads();

        // ---- consumers: 4 k16 steps ----
#pragma unroll
        for (int ks = 0; ks < 4; ks++) {
            uint32_t af[2][4];
#pragma unroll
            for (int mi = 0; mi < 2; mi++)
                ldsm_x4(af[mi], aB + swz128((uint32_t)(aRow[mi] * 128 + (ks * 16 + aKof) * 2)));

            uint32_t bf_[4][4];
#pragma unroll
            for (int q = 0; q < 4; q++)
                ldsm_x4(bf_[q], bhB + swz128((uint32_t)((bRowBase + q * 16) * 128 +
                                                        (ks * 16 + bKof) * 2)));
#pragma unroll
            for (int mi = 0; mi < 2; mi++)
#pragma unroll
                for (int g = 0; g < 8; g++)
                    mma16816(acc[mi][g], af[mi], &bf_[g >> 1][(g & 1) * 2]);

#pragma unroll
            for (int q = 0; q < 4; q++)
                ldsm_x4(bf_[q], blB + swz128((uint32_t)((bRowBase + q * 16) * 128 +
                                                        (ks * 16 + bKof) * 2)));
#pragma unroll
            for (int mi = 0; mi < 2; mi++)
#pragma unroll
                for (int g = 0; g < 8; g++)
                    mma16816(acc[mi][g], af[mi], &bf_[g >> 1][(g & 1) * 2]);
        }
        __syncthreads();
    }

    // ---- epilogue: bias add + fp32 store ----
#pragma unroll
    for (int mi = 0; mi < 2; mi++) {
        const int row = m0 + mrow0 + mi * 16 + (lane >> 2);
#pragma unroll
        for (int g = 0; g < 8; g++) {
            const int col = n0 + ncol0 + g * 8 + (lane & 3) * 2;
            const float b0 = bias[col], b1 = bias[col + 1];
            *(float2*)(C + (size_t)row * Ntot + col) =
                make_float2(acc[mi][g][0] + b0, acc[mi][g][1] + b1);
            *(float2*)(C + (size_t)(row + 8) * Ntot + col) =
                make_float2(acc[mi][g][2] + b0, acc[mi][g][3] + b1);
        }
    }
}

// ---------------------------------------------------------------------------
// SIMT tiled GEMM (layer 2):  C = op(A) . Bmat^T + bias
//   mode 1: op(v) = relu(g*(v - mean[row/statdiv]) * rstd[row/statdiv] + be)
// ---------------------------------------------------------------------------
__global__ __launch_bounds__(256, 2)
void gemm_k(const float* __restrict__ A, const float* __restrict__ Bm,
            const float* __restrict__ bias, float* __restrict__ C,
            int M, int Ntot, int K, int mode,
            const float* __restrict__ meanp, const float* __restrict__ rstdp,
            int statdiv, const float* __restrict__ gptr,
            const float* __restrict__ beptr)
{
    __shared__ float As[16][132];
    __shared__ float Bs[16][132];

    const int tid = threadIdx.x;
    const int m0 = blockIdx.x * 128;
    const int n0 = blockIdx.y * 128;

    const int lr = tid >> 1;
    const int lc = (tid & 1) * 8;

    const float* pA = A  + (size_t)(m0 + lr) * K + lc;
    const float* pB = Bm + (size_t)(n0 + lr) * K + lc;

    float rm = 0.f, rr = 0.f, gg = 0.f, bb = 0.f;
    if (mode == 1) {
        const int si = (m0 + lr) / statdiv;
        rm = meanp[si]; rr = rstdp[si];
        gg = *gptr;     bb = *beptr;
    }

    float acc[8][8];
#pragma unroll
    for (int i = 0; i < 8; i++)
#pragma unroll
        for (int j = 0; j < 8; j++) acc[i][j] = 0.f;

    const int ty = tid >> 4;
    const int tx = tid & 15;

    for (int k0 = 0; k0 < K; k0 += 16) {
        float4 a0 = *(const float4*)(pA + k0);
        float4 a1 = *(const float4*)(pA + k0 + 4);
        float4 b0 = *(const float4*)(pB + k0);
        float4 b1 = *(const float4*)(pB + k0 + 4);

        float av[8] = {a0.x, a0.y, a0.z, a0.w, a1.x, a1.y, a1.z, a1.w};
#pragma unroll
        for (int j = 0; j < 8; j++) {
            float v = av[j];
            if (mode == 0) {
                float afv = fabsf(v);
                v = (afv >= 1e-12f) ? copysignf(1.f, v) : v * 1e12f;
            } else {
                v = fmaxf(gg * (v - rm) * rr + bb, 0.f);
            }
            As[lc + j][lr] = v;
        }
        float bv[8] = {b0.x, b0.y, b0.z, b0.w, b1.x, b1.y, b1.z, b1.w};
#pragma unroll
        for (int j = 0; j < 8; j++) Bs[lc + j][lr] = bv[j];

        __syncthreads();

#pragma unroll
        for (int kk = 0; kk < 16; kk++) {
            float a[8], b[8];
#pragma unroll
            for (int i = 0; i < 8; i++) a[i] = As[kk][ty * 8 + i];
#pragma unroll
            for (int j = 0; j < 8; j++) b[j] = Bs[kk][tx * 8 + j];
#pragma unroll
            for (int i = 0; i < 8; i++)
#pragma unroll
                for (int j = 0; j < 8; j++) acc[i][j] += a[i] * b[j];
        }
        __syncthreads();
    }

    float bs[8];
#pragma unroll
    for (int j = 0; j < 8; j++) bs[j] = bias[n0 + tx * 8 + j];
#pragma unroll
    for (int i = 0; i < 8; i++) {
        float* cp = C + (size_t)(m0 + ty * 8 + i) * Ntot + n0 + tx * 8;
        float4 o0 = make_float4(acc[i][0] + bs[0], acc[i][1] + bs[1],
                                acc[i][2] + bs[2], acc[i][3] + bs[3]);
        float4 o1 = make_float4(acc[i][4] + bs[4], acc[i][5] + bs[5],
                                acc[i][6] + bs[6], acc[i][7] + bs[7]);
        *(float4*)cp       = o0;
        *(float4*)(cp + 4) = o1;
    }
}

// ---------------------------------------------------------------------------
// Attention layer 1 (H=256). One block per graph node b, 256 threads.
// ---------------------------------------------------------------------------
__global__ void attn1_k(const float* __restrict__ nbh, const float* __restrict__ xh,
                        const float* __restrict__ a_self, const float* __restrict__ a_nb,
                        float* __restrict__ x1, float* __restrict__ mb,
                        float* __restrict__ rb, float* __restrict__ px,
                        float* __restrict__ pxq)
{
    const int b = blockIdx.x, tid = threadIdx.x;
    __shared__ float red[256];
    __shared__ float sc[64];

    const float* base = nbh + (size_t)b * Nn * H1n;

    red[tid] = xh[b * H1n + tid] * a_self[tid];
    __syncthreads();
    for (int s = 128; s > 0; s >>= 1) {
        if (tid < s) red[tid] += red[tid + s];
        __syncthreads();
    }
    const float sx = red[0];
    __syncthreads();

    const int w = tid >> 5, l = tid & 31;
#pragma unroll
    for (int nn = 0; nn < 8; nn++) {
        const int n = w * 8 + nn;
        const float* row = base + n * H1n;
        float acc = 0.f;
#pragma unroll
        for (int j = 0; j < 8; j++) acc += row[l + 32 * j] * a_nb[l + 32 * j];
#pragma unroll
        for (int o = 16; o > 0; o >>= 1) acc += __shfl_down_sync(0xffffffffu, acc, o);
        if (l == 0) sc[n] = sx + acc;
    }
    __syncthreads();

    if (w == 0) {
        float v0 = sc[l], v1 = sc[l + 32];
        v0 = v0 > 0.f ? v0 : ALPHA_LRELU * v0;
        v1 = v1 > 0.f ? v1 : ALPHA_LRELU * v1;
        float mx = fmaxf(v0, v1);
#pragma unroll
        for (int o = 16; o > 0; o >>= 1) mx = fmaxf(mx, __shfl_xor_sync(0xffffffffu, mx, o));
        float e0 = __expf(v0 - mx), e1 = __expf(v1 - mx);
        float s = e0 + e1;
#pragma unroll
        for (int o = 16; o > 0; o >>= 1) s += __shfl_xor_sync(0xffffffffu, s, o);
        const float inv = 1.f / s;
        sc[l] = e0 * inv; sc[l + 32] = e1 * inv;
    }
    __syncthreads();

    float acc = 0.f, sm = 0.f, sq = 0.f;
#pragma unroll 8
    for (int n = 0; n < Nn; n++) {
        const float v = base[n * H1n + tid];
        acc += sc[n] * v;
        sm += v;
        sq += v * v;
    }
    x1[b * H1n + tid] = acc;

    red[tid] = sm; __syncthreads();
    for (int s = 128; s > 0; s >>= 1) { if (tid < s) red[tid] += red[tid + s]; __syncthreads(); }
    const float S = red[0]; __syncthreads();
    red[tid] = sq; __syncthreads();
    for (int s = 128; s > 0; s >>= 1) { if (tid < s) red[tid] += red[tid + s]; __syncthreads(); }
    const float SQ = red[0]; __syncthreads();
    red[tid] = acc; __syncthreads();
    for (int s = 128; s > 0; s >>= 1) { if (tid < s) red[tid] += red[tid + s]; __syncthreads(); }
    const float SX = red[0]; __syncthreads();
    red[tid] = acc * acc; __syncthreads();
    for (int s = 128; s > 0; s >>= 1) { if (tid < s) red[tid] += red[tid + s]; __syncthreads(); }
    const float SXQ = red[0];

    if (tid == 0) {
        const float inv_cnt = 1.f / (float)(Nn * H1n);
        const float mean = S * inv_cnt;
        const float var  = SQ * inv_cnt - mean * mean;
        mb[b] = mean;
        rb[b] = rsqrtf(fmaxf(var, 0.f) + BN_EPS);
        px[b]  = SX;
        pxq[b] = SXQ;
    }
}

// ---------------------------------------------------------------------------
// Attention layer 2 (H=128). One block per node, 128 threads.
// ---------------------------------------------------------------------------
__global__ void attn2_k(const float* __restrict__ nbh, const float* __restrict__ xh,
                        const float* __restrict__ a_self, const float* __restrict__ a_nb,
                        float* __restrict__ x2, float* __restrict__ px,
                        float* __restrict__ pxq)
{
    const int b = blockIdx.x, tid = threadIdx.x;
    __shared__ float red[128];
    __shared__ float sc[64];

    const float* base = nbh + (size_t)b * Nn * H2n;

    red[tid] = xh[b * H2n + tid] * a_self[tid];
    __syncthreads();
    for (int s = 64; s > 0; s >>= 1) { if (tid < s) red[tid] += red[tid + s]; __syncthreads(); }
    const float sx = red[0];
    __syncthreads();

    const int w = tid >> 5, l = tid & 31;
#pragma unroll
    for (int nn = 0; nn < 16; nn++) {
        const int n = w * 16 + nn;
        const float* row = base + n * H2n;
        float acc = 0.f;
#pragma unroll
        for (int j = 0; j < 4; j++) acc += row[l + 32 * j] * a_nb[l + 32 * j];
#pragma unroll
        for (int o = 16; o > 0; o >>= 1) acc += __shfl_down_sync(0xffffffffu, acc, o);
        if (l == 0) sc[n] = sx + acc;
    }
    __syncthreads();

    if (w == 0) {
        float v0 = sc[l], v1 = sc[l + 32];
        v0 = v0 > 0.f ? v0 : ALPHA_LRELU * v0;
        v1 = v1 > 0.f ? v1 : ALPHA_LRELU * v1;
        float mx = fmaxf(v0, v1);
#pragma unroll
        for (int o = 16; o > 0; o >>= 1) mx = fmaxf(mx, __shfl_xor_sync(0xffffffffu, mx, o));
        float e0 = __expf(v0 - mx), e1 = __expf(v1 - mx);
        float s = e0 + e1;
#pragma unroll
        for (int o = 16; o > 0; o >>= 1) s += __shfl_xor_sync(0xffffffffu, s, o);
        const float inv = 1.f / s;
        sc[l] = e0 * inv; sc[l + 32] = e1 * inv;
    }
    __syncthreads();

    float acc = 0.f;
#pragma unroll 8
    for (int n = 0; n < Nn; n++) acc += sc[n] * base[n * H2n + tid];
    x2[b * H2n + tid] = acc;

    red[tid] = acc; __syncthreads();
    for (int s = 64; s > 0; s >>= 1) { if (tid < s) red[tid] += red[tid + s]; __syncthreads(); }
    const float SX = red[0]; __syncthreads();
    red[tid] = acc * acc; __syncthreads();
    for (int s = 64; s > 0; s >>= 1) { if (tid < s) red[tid] += red[tid + s]; __syncthreads(); }
    const float SXQ = red[0];

    if (tid == 0) { px[b] = SX; pxq[b] = SXQ; }
}

// ---------------------------------------------------------------------------
// Finalize global BN stats from per-block partials (1 block, 1024 threads).
// ---------------------------------------------------------------------------
__global__ void bnstats_k(const float* __restrict__ px, const float* __restrict__ pxq,
                          float* __restrict__ bn, float invcnt)
{
    __shared__ float r1[1024];
    __shared__ float r2[1024];
    const int t = threadIdx.x;
    r1[t] = px[t]; r2[t] = pxq[t];
    __syncthreads();
    for (int s = 512; s > 0; s >>= 1) {
        if (t < s) { r1[t] += r1[t + s]; r2[t] += r2[t + s]; }
        __syncthreads();
    }
    if (t == 0) {
        const float mean = r1[0] * invcnt;
        const float var  = r2[0] * invcnt - mean * mean;
        bn[0] = mean;
        bn[1] = rsqrtf(fmaxf(var, 0.f) + BN_EPS);
    }
}

// ---------------------------------------------------------------------------
// Final: BN-ReLU x2 + logits. One block per b, 128 threads.
// ---------------------------------------------------------------------------
__global__ void logits_k(const float* __restrict__ x2, const float* __restrict__ bn2,
                         const float* __restrict__ gptr, const float* __restrict__ beptr,
                         const float* __restrict__ Wl, const float* __restrict__ bl,
                         float* __restrict__ out)
{
    const int b = blockIdx.x, t = threadIdx.x;
    __shared__ float xn[H2n];
    const float m = bn2[0], r = bn2[1], g = gptr[0], be = beptr[0];
    float v = x2[b * H2n + t];
    xn[t] = fmaxf(g * (v - m) * r + be, 0.f);
    __syncthreads();

    const float* wr = Wl + t * H2n;
    float acc = bl[t];
#pragma unroll 8
    for (int h = 0; h < H2n; h++) acc += xn[h] * wr[h];
    out[b * NCn + t] = acc;
}

// ---------------------------------------------------------------------------
// Launch
// ---------------------------------------------------------------------------
extern "C" void kernel_launch(void* const* d_in, const int* in_sizes, int n_in,
                              void* d_out, int out_size)
{
    (void)in_sizes; (void)n_in; (void)out_size;
    const float* x   = (const float*)d_in[0];
    const float* nb  = (const float*)d_in[1];
    const float* W1  = (const float*)d_in[2];
    const float* b1  = (const float*)d_in[3];
    const float* a11 = (const float*)d_in[4];
    const float* a12 = (const float*)d_in[5];
    const float* g1  = (const float*)d_in[6];
    const float* be1 = (const float*)d_in[7];
    const float* W2  = (const float*)d_in[8];
    const float* b2  = (const float*)d_in[9];
    const float* a21 = (const float*)d_in[10];
    const float* a22 = (const float*)d_in[11];
    const float* g2  = (const float*)d_in[12];
    const float* be2 = (const float*)d_in[13];
    const float* Wl  = (const float*)d_in[14];
    const float* bl  = (const float*)d_in[15];
    float* out = (float*)d_out;

    float *nbh1, *xh1, *x1, *mb1, *rb1, *px1, *pxq1, *bn1;
    float *nbh2, *xh2, *x2, *px2, *pxq2, *bn2;
    __nv_bfloat16 *w1hi, *w1lo;
    cudaGetSymbolAddress((void**)&nbh1, g_nbh1);
    cudaGetSymbolAddress((void**)&xh1,  g_xh1);
    cudaGetSymbolAddress((void**)&x1,   g_x1);
    cudaGetSymbolAddress((void**)&mb1,  g_mb1);
    cudaGetSymbolAddress((void**)&rb1,  g_rb1);
    cudaGetSymbolAddress((void**)&px1,  g_px1);
    cudaGetSymbolAddress((void**)&pxq1, g_pxq1);
    cudaGetSymbolAddress((void**)&bn1,  g_bn1);
    cudaGetSymbolAddress((void**)&nbh2, g_nbh2);
    cudaGetSymbolAddress((void**)&xh2,  g_xh2);
    cudaGetSymbolAddress((void**)&x2,   g_x2);
    cudaGetSymbolAddress((void**)&px2,  g_px2);
    cudaGetSymbolAddress((void**)&pxq2, g_pxq2);
    cudaGetSymbolAddress((void**)&bn2,  g_bn2);
    cudaGetSymbolAddress((void**)&w1hi, g_w1hi);
    cudaGetSymbolAddress((void**)&w1lo, g_w1lo);

    // W1 -> bf16 hi/lo split
    wsplit_k<<<256, 1024>>>(W1, w1hi, w1lo, H1n * Fn);

    // Layer 1 GEMMs on tensor cores (mma.sync): sign(input) @ (Whi+Wlo)^T + b1
    tc_gemm1_k<<<dim3(Mn / 128, H1n / 128), 256>>>(nb, w1hi, w1lo, b1, nbh1, Fn, H1n);
    tc_gemm1_k<<<dim3(Bn / 128, H1n / 128), 256>>>(x,  w1hi, w1lo, b1, xh1, Fn, H1n);

    // Attention 1 + per-node neighbor BN stats + x1 partial stats
    attn1_k<<<Bn, 256>>>(nbh1, xh1, a11, a12, x1, mb1, rb1, px1, pxq1);
    bnstats_k<<<1, 1024>>>(px1, pxq1, bn1, 1.f / (float)(Bn * H1n));

    // Layer 2 GEMMs (SIMT): BN-ReLU(input) @ W2^T + b2
    gemm_k<<<dim3(Mn / 128, H2n / 128), 256>>>(nbh1, W2, b2, nbh2, Mn, H2n, H1n, 1,
                                               mb1, rb1, Nn, g1, be1);
    gemm_k<<<dim3(Bn / 128, H2n / 128), 256>>>(x1, W2, b2, xh2, Bn, H2n, H1n, 1,
                                               bn1, bn1 + 1, 1 << 30, g1, be1);
    // Attention 2 + x2 partial stats
    attn2_k<<<Bn, 128>>>(nbh2, xh2, a21, a22, x2, px2, pxq2);
    bnstats_k<<<1, 1024>>>(px2, pxq2, bn2, 1.f / (float)(Bn * H2n));

    // BN-ReLU + classifier
    logits_k<<<Bn, 128>>>(x2, bn2, g2, be2, Wl, bl, out);
}

// round 4
// speedup vs baseline: 2.1148x; 1.2196x over previous
#include <cuda_runtime.h>
#include <cuda_bf16.h>
#include <cstdint>
#include <cstddef>

// Problem dims (fixed by the dataset)
#define Bn   1024
#define Nn   64
#define Fn   1024
#define H1n  256
#define H2n  128
#define NCn  128
#define Mn   (Bn*Nn)      // 65536
#define ALPHA_LRELU 0.2f
#define BN_EPS 1e-5f

// ---------------------------------------------------------------------------
// Scratch (static device globals — allocation-free, per harness rules)
// ---------------------------------------------------------------------------
__device__ float g_nbh1[(size_t)Mn * H1n];   // 64 MB
__device__ float g_xh1 [Bn * H1n];
__device__ float g_x1  [Bn * H1n];
__device__ float g_mb1 [Bn];
__device__ float g_rb1 [Bn];
__device__ float g_px1 [Bn];
__device__ float g_pxq1[Bn];
__device__ float g_bn1 [2];
__device__ float g_nbh2[(size_t)Mn * H2n];   // 32 MB
__device__ float g_xh2 [Bn * H2n];
__device__ float g_x2  [Bn * H2n];
__device__ float g_px2 [Bn];
__device__ float g_pxq2[Bn];
__device__ float g_bn2 [2];
__device__ __nv_bfloat16 g_w1hi[H1n * Fn];   // 512 KB
__device__ __nv_bfloat16 g_w1lo[H1n * Fn];   // 512 KB
__device__ __nv_bfloat16 g_w2hi[H2n * H1n];  // 64 KB
__device__ __nv_bfloat16 g_w2lo[H2n * H1n];  // 64 KB

// ---------------------------------------------------------------------------
// PTX helpers: ldmatrix + mma.sync + cp.async (arch-stable)
// ---------------------------------------------------------------------------
__device__ __forceinline__ uint32_t smem_u32(const void* p) {
    uint32_t a;
    asm("{ .reg .u64 t; cvta.to.shared.u64 t, %1; cvt.u32.u64 %0, t; }" : "=r"(a) : "l"(p));
    return a;
}
__device__ __forceinline__ void ldsm_x4(uint32_t* r, uint32_t addr) {
    asm volatile("ldmatrix.sync.aligned.m8n8.x4.shared.b16 {%0,%1,%2,%3}, [%4];"
                 : "=r"(r[0]), "=r"(r[1]), "=r"(r[2]), "=r"(r[3]) : "r"(addr));
}
__device__ __forceinline__ void mma16816(float* c, const uint32_t* a, const uint32_t* b) {
    asm volatile("mma.sync.aligned.m16n8k16.row.col.f32.bf16.bf16.f32 "
                 "{%0,%1,%2,%3}, {%4,%5,%6,%7}, {%8,%9}, {%0,%1,%2,%3};"
                 : "+f"(c[0]), "+f"(c[1]), "+f"(c[2]), "+f"(c[3])
                 : "r"(a[0]), "r"(a[1]), "r"(a[2]), "r"(a[3]), "r"(b[0]), "r"(b[1]));
}
__device__ __forceinline__ void cp16(uint32_t dst, const void* src) {
    asm volatile("cp.async.cg.shared.global [%0], [%1], 16;" :: "r"(dst), "l"(src) : "memory");
}
#define CP_COMMIT() asm volatile("cp.async.commit_group;" ::: "memory")
#define CP_WAIT0()  asm volatile("cp.async.wait_group 0;" ::: "memory")

__device__ __forceinline__ uint32_t swz128(uint32_t off) { return off ^ ((off >> 3) & 0x70); }

__device__ __forceinline__ uint32_t pack_sign_bf16x2(float a, float b) {
    float sa = (fabsf(a) >= 1e-12f) ? copysignf(1.f, a) : a * 1e12f;
    float sb = (fabsf(b) >= 1e-12f) ? copysignf(1.f, b) : b * 1e12f;
    __nv_bfloat162 h = __floats2bfloat162_rn(sa, sb);
    return *reinterpret_cast<uint32_t*>(&h);
}
__device__ __forceinline__ uint32_t pack_bf16x2(float a, float b) {
    __nv_bfloat162 h = __floats2bfloat162_rn(a, b);
    return *reinterpret_cast<uint32_t*>(&h);
}

// ---------------------------------------------------------------------------
// W split: Whi = bf16(W), Wlo = bf16(W - Whi)
// ---------------------------------------------------------------------------
__global__ void wsplit_k(const float* __restrict__ W, __nv_bfloat16* __restrict__ hi,
                         __nv_bfloat16* __restrict__ lo, int n)
{
    int i = blockIdx.x * blockDim.x + threadIdx.x;
    if (i < n) {
        float w = W[i];
        __nv_bfloat16 h = __float2bfloat16_rn(w);
        hi[i] = h;
        lo[i] = __float2bfloat16_rn(w - __bfloat162float(h));
    }
}

// ---------------------------------------------------------------------------
// GEMM1 (mma.sync, pipelined): C[M,256] = sign(A[M,1024]) @ W1^T + b1.
// Split-bf16 W (hi+lo), exact ±1 A. CTA tile 128x128, K-chunk 64, 8 warps.
// Double-buffered SMEM (96KB dyn), cp.async for B tiles, reg-prefetch A,
// one __syncthreads per chunk.
// SMEM layout: [A0 16K][A1 16K][Bh0 16K][Bh1 16K][Bl0 16K][Bl1 16K]
// ---------------------------------------------------------------------------
#define G1_SMEM (6 * 16384)

__global__ __launch_bounds__(256)
void tc_gemm1_k(const float* __restrict__ A, const __nv_bfloat16* __restrict__ Whi,
                const __nv_bfloat16* __restrict__ Wlo, const float* __restrict__ bias,
                float* __restrict__ C, int K, int Ntot)
{
    extern __shared__ char smem[];
    const uint32_t sb = smem_u32(smem);

    const int tid = threadIdx.x;
    const int wid = tid >> 5, lane = tid & 31;
    const int m0 = blockIdx.x * 128;
    const int n0 = blockIdx.y * 128;

    const int mrow0 = (wid >> 1) * 32;
    const int ncol0 = (wid & 1) * 64;

    const int r  = tid >> 1;
    const int c0 = (tid & 1) * 32;
    const float* aSrc = A + (size_t)(m0 + r) * K + c0;
    const __nv_bfloat16* hSrc = Whi + (size_t)(n0 + r) * K + c0;
    const __nv_bfloat16* lSrc = Wlo + (size_t)(n0 + r) * K + c0;

    uint32_t sOff[4];
#pragma unroll
    for (int j = 0; j < 4; j++)
        sOff[j] = swz128((uint32_t)(r * 128 + (c0 + j * 8) * 2));

    float acc[2][8][4];
#pragma unroll
    for (int i = 0; i < 2; i++)
#pragma unroll
        for (int g = 0; g < 8; g++)
#pragma unroll
            for (int q = 0; q < 4; q++) acc[i][g][q] = 0.f;

    const int aRow[2] = { mrow0 + (lane & 15), mrow0 + 16 + (lane & 15) };
    const int aKof   = (lane >> 4) << 3;
    const int bRowBase = ncol0 + (lane & 7) + ((lane >> 4) << 3);
    const int bKof   = ((lane >> 3) & 1) << 3;

    // ---- prologue: issue B chunk0 into buf0, load+pack A chunk0 ----
    uint4 pa[4];
#pragma unroll
    for (int j = 0; j < 4; j++) {
        cp16(sb + 32768 + sOff[j], hSrc + j * 8);
        cp16(sb + 65536 + sOff[j], lSrc + j * 8);
    }
    CP_COMMIT();
#pragma unroll
    for (int j = 0; j < 4; j++) {
        float4 f0 = *(const float4*)(aSrc + j * 8);
        float4 f1 = *(const float4*)(aSrc + j * 8 + 4);
        pa[j].x = pack_sign_bf16x2(f0.x, f0.y);
        pa[j].y = pack_sign_bf16x2(f0.z, f0.w);
        pa[j].z = pack_sign_bf16x2(f1.x, f1.y);
        pa[j].w = pack_sign_bf16x2(f1.z, f1.w);
    }

    const int nCh = K / 64;   // 16
    for (int ch = 0; ch < nCh; ch++) {
        const int buf = ch & 1;
        const uint32_t aB  = sb + buf * 16384;
        const uint32_t bhB = sb + 32768 + buf * 16384;
        const uint32_t blB = sb + 65536 + buf * 16384;

        // store prefetched A
#pragma unroll
        for (int j = 0; j < 4; j++)
            *(uint4*)(smem + buf * 16384 + sOff[j]) = pa[j];

        CP_WAIT0();
        __syncthreads();

        // issue next chunk (overlaps with mma below)
        if (ch + 1 < nCh) {
            const int nbuf = buf ^ 1;
            const int k1 = (ch + 1) * 64;
#pragma unroll
            for (int j = 0; j < 4; j++) {
                cp16(sb + 32768 + nbuf * 16384 + sOff[j], hSrc + k1 + j * 8);
                cp16(sb + 65536 + nbuf * 16384 + sOff[j], lSrc + k1 + j * 8);
            }
            CP_COMMIT();
#pragma unroll
            for (int j = 0; j < 4; j++) {
                float4 f0 = *(const float4*)(aSrc + k1 + j * 8);
                float4 f1 = *(const float4*)(aSrc + k1 + j * 8 + 4);
                pa[j].x = pack_sign_bf16x2(f0.x, f0.y);
                pa[j].y = pack_sign_bf16x2(f0.z, f0.w);
                pa[j].z = pack_sign_bf16x2(f1.x, f1.y);
                pa[j].w = pack_sign_bf16x2(f1.z, f1.w);
            }
        }

        // consume
#pragma unroll
        for (int ks = 0; ks < 4; ks++) {
            uint32_t af[2][4];
#pragma unroll
            for (int mi = 0; mi < 2; mi++)
                ldsm_x4(af[mi], aB + swz128((uint32_t)(aRow[mi] * 128 + (ks * 16 + aKof) * 2)));

            uint32_t bf_[4][4];
#pragma unroll
            for (int q = 0; q < 4; q++)
                ldsm_x4(bf_[q], bhB + swz128((uint32_t)((bRowBase + q * 16) * 128 +
                                                        (ks * 16 + bKof) * 2)));
#pragma unroll
            for (int mi = 0; mi < 2; mi++)
#pragma unroll
                for (int g = 0; g < 8; g++)
                    mma16816(acc[mi][g], af[mi], &bf_[g >> 1][(g & 1) * 2]);

#pragma unroll
            for (int q = 0; q < 4; q++)
                ldsm_x4(bf_[q], blB + swz128((uint32_t)((bRowBase + q * 16) * 128 +
                                                        (ks * 16 + bKof) * 2)));
#pragma unroll
            for (int mi = 0; mi < 2; mi++)
#pragma unroll
                for (int g = 0; g < 8; g++)
                    mma16816(acc[mi][g], af[mi], &bf_[g >> 1][(g & 1) * 2]);
        }
        __syncthreads();
    }

    // ---- epilogue: bias add + fp32 store ----
#pragma unroll
    for (int mi = 0; mi < 2; mi++) {
        const int row = m0 + mrow0 + mi * 16 + (lane >> 2);
#pragma unroll
        for (int g = 0; g < 8; g++) {
            const int col = n0 + ncol0 + g * 8 + (lane & 3) * 2;
            const float b0 = bias[col], b1 = bias[col + 1];
            *(float2*)(C + (size_t)row * Ntot + col) =
                make_float2(acc[mi][g][0] + b0, acc[mi][g][1] + b1);
            *(float2*)(C + (size_t)(row + 8) * Ntot + col) =
                make_float2(acc[mi][g][2] + b0, acc[mi][g][3] + b1);
        }
    }
}

// ---------------------------------------------------------------------------
// GEMM2 (mma.sync): C[M,128] = BN_ReLU(A[M,256]) @ W2^T + b2.
// A split hi/lo in producer; C = Ahi*Whi + Ahi*Wlo + Alo*Whi.
// CTA tile 128x128 (N=128 full), K-chunk 64 (4 chunks), single-buffered.
// SMEM: [Ahi 16K][Alo 16K][Bhi 16K][Blo 16K] = 64KB dynamic.
// ---------------------------------------------------------------------------
#define G2_SMEM (4 * 16384)

__global__ __launch_bounds__(256)
void tc_gemm2_k(const float* __restrict__ A, const __nv_bfloat16* __restrict__ Whi,
                const __nv_bfloat16* __restrict__ Wlo, const float* __restrict__ bias,
                float* __restrict__ C,
                const float* __restrict__ meanp, const float* __restrict__ rstdp,
                int statdiv, const float* __restrict__ gptr,
                const float* __restrict__ beptr)
{
    extern __shared__ char smem[];
    const uint32_t sb = smem_u32(smem);
    const uint32_t ahB = sb, alB = sb + 16384, bhB = sb + 32768, blB = sb + 49152;

    const int tid = threadIdx.x;
    const int wid = tid >> 5, lane = tid & 31;
    const int m0 = blockIdx.x * 128;

    const int mrow0 = (wid >> 1) * 32;
    const int ncol0 = (wid & 1) * 64;

    const int r  = tid >> 1;
    const int c0 = (tid & 1) * 32;
    const float* aSrc = A + (size_t)(m0 + r) * H1n + c0;
    const __nv_bfloat16* hSrc = Whi + (size_t)r * H1n + c0;   // n-row = r (128 rows)
    const __nv_bfloat16* lSrc = Wlo + (size_t)r * H1n + c0;

    const float rm = meanp[(m0 + r) / statdiv];
    const float rr = rstdp[(m0 + r) / statdiv];
    const float gg = *gptr, bb = *beptr;

    uint32_t sOff[4];
#pragma unroll
    for (int j = 0; j < 4; j++)
        sOff[j] = swz128((uint32_t)(r * 128 + (c0 + j * 8) * 2));

    float acc[2][8][4];
#pragma unroll
    for (int i = 0; i < 2; i++)
#pragma unroll
        for (int g = 0; g < 8; g++)
#pragma unroll
            for (int q = 0; q < 4; q++) acc[i][g][q] = 0.f;

    const int aRow[2] = { mrow0 + (lane & 15), mrow0 + 16 + (lane & 15) };
    const int aKof   = (lane >> 4) << 3;
    const int bRowBase = ncol0 + (lane & 7) + ((lane >> 4) << 3);
    const int bKof   = ((lane >> 3) & 1) << 3;

    for (int k0 = 0; k0 < H1n; k0 += 64) {
        // ---- producers: BN-ReLU + hi/lo split for A, raw copies for W2 ----
#pragma unroll
        for (int j = 0; j < 4; j++) {
            float4 f0 = *(const float4*)(aSrc + k0 + j * 8);
            float4 f1 = *(const float4*)(aSrc + k0 + j * 8 + 4);
            float v[8] = {f0.x, f0.y, f0.z, f0.w, f1.x, f1.y, f1.z, f1.w};
            float hi[8], lo[8];
#pragma unroll
            for (int e = 0; e < 8; e++) {
                float t = fmaxf(gg * (v[e] - rm) * rr + bb, 0.f);
                __nv_bfloat16 h = __float2bfloat16_rn(t);
                hi[e] = __bfloat162float(h);
                lo[e] = t - hi[e];
            }
            uint4 oh, ol;
            oh.x = pack_bf16x2(hi[0], hi[1]); oh.y = pack_bf16x2(hi[2], hi[3]);
            oh.z = pack_bf16x2(hi[4], hi[5]); oh.w = pack_bf16x2(hi[6], hi[7]);
            ol.x = pack_bf16x2(lo[0], lo[1]); ol.y = pack_bf16x2(lo[2], lo[3]);
            ol.z = pack_bf16x2(lo[4], lo[5]); ol.w = pack_bf16x2(lo[6], lo[7]);
            *(uint4*)(smem + sOff[j]) = oh;
            *(uint4*)(smem + 16384 + sOff[j]) = ol;
            uint4 vh = *(const uint4*)(hSrc + k0 + j * 8);
            uint4 vl = *(const uint4*)(lSrc + k0 + j * 8);
            *(uint4*)(smem + 32768 + sOff[j]) = vh;
            *(uint4*)(smem + 49152 + sOff[j]) = vl;
        }
        __syncthreads();

        // ---- consumers ----
#pragma unroll
        for (int ks = 0; ks < 4; ks++) {
            uint32_t ah[2][4], al[2][4];
#pragma unroll
            for (int mi = 0; mi < 2; mi++) {
                const uint32_t ro = swz128((uint32_t)(aRow[mi] * 128 + (ks * 16 + aKof) * 2));
                ldsm_x4(ah[mi], ahB + ro);
                ldsm_x4(al[mi], alB + ro);
            }
            uint32_t bf_[4][4];
#pragma unroll
            for (int q = 0; q < 4; q++)
                ldsm_x4(bf_[q], bhB + swz128((uint32_t)((bRowBase + q * 16) * 128 +
                                                        (ks * 16 + bKof) * 2)));
            // Ahi*Whi + Alo*Whi
#pragma unroll
            for (int mi = 0; mi < 2; mi++)
#pragma unroll
                for (int g = 0; g < 8; g++) {
                    mma16816(acc[mi][g], ah[mi], &bf_[g >> 1][(g & 1) * 2]);
                    mma16816(acc[mi][g], al[mi], &bf_[g >> 1][(g & 1) * 2]);
                }
            // Ahi*Wlo
#pragma unroll
            for (int q = 0; q < 4; q++)
                ldsm_x4(bf_[q], blB + swz128((uint32_t)((bRowBase + q * 16) * 128 +
                                                        (ks * 16 + bKof) * 2)));
#pragma unroll
            for (int mi = 0; mi < 2; mi++)
#pragma unroll
                for (int g = 0; g < 8; g++)
                    mma16816(acc[mi][g], ah[mi], &bf_[g >> 1][(g & 1) * 2]);
        }
        __syncthreads();
    }

    // ---- epilogue ----
#pragma unroll
    for (int mi = 0; mi < 2; mi++) {
        const int row = m0 + mrow0 + mi * 16 + (lane >> 2);
#pragma unroll
        for (int g = 0; g < 8; g++) {
            const int col = ncol0 + g * 8 + (lane & 3) * 2;
            const float b0 = bias[col], b1 = bias[col + 1];
            *(float2*)(C + (size_t)row * H2n + col) =
                make_float2(acc[mi][g][0] + b0, acc[mi][g][1] + b1);
            *(float2*)(C + (size_t)(row + 8) * H2n + col) =
                make_float2(acc[mi][g][2] + b0, acc[mi][g][3] + b1);
        }
    }
}

// ---------------------------------------------------------------------------
// Attention layer 1 (H=256). One block per graph node b, 256 threads.
// ---------------------------------------------------------------------------
__global__ void attn1_k(const float* __restrict__ nbh, const float* __restrict__ xh,
                        const float* __restrict__ a_self, const float* __restrict__ a_nb,
                        float* __restrict__ x1, float* __restrict__ mb,
                        float* __restrict__ rb, float* __restrict__ px,
                        float* __restrict__ pxq)
{
    const int b = blockIdx.x, tid = threadIdx.x;
    __shared__ float red[256];
    __shared__ float sc[64];

    const float* base = nbh + (size_t)b * Nn * H1n;

    red[tid] = xh[b * H1n + tid] * a_self[tid];
    __syncthreads();
    for (int s = 128; s > 0; s >>= 1) {
        if (tid < s) red[tid] += red[tid + s];
        __syncthreads();
    }
    const float sx = red[0];
    __syncthreads();

    const int w = tid >> 5, l = tid & 31;
#pragma unroll
    for (int nn = 0; nn < 8; nn++) {
        const int n = w * 8 + nn;
        const float* row = base + n * H1n;
        float acc = 0.f;
#pragma unroll
        for (int j = 0; j < 8; j++) acc += row[l + 32 * j] * a_nb[l + 32 * j];
#pragma unroll
        for (int o = 16; o > 0; o >>= 1) acc += __shfl_down_sync(0xffffffffu, acc, o);
        if (l == 0) sc[n] = sx + acc;
    }
    __syncthreads();

    if (w == 0) {
        float v0 = sc[l], v1 = sc[l + 32];
        v0 = v0 > 0.f ? v0 : ALPHA_LRELU * v0;
        v1 = v1 > 0.f ? v1 : ALPHA_LRELU * v1;
        float mx = fmaxf(v0, v1);
#pragma unroll
        for (int o = 16; o > 0; o >>= 1) mx = fmaxf(mx, __shfl_xor_sync(0xffffffffu, mx, o));
        float e0 = __expf(v0 - mx), e1 = __expf(v1 - mx);
        float s = e0 + e1;
#pragma unroll
        for (int o = 16; o > 0; o >>= 1) s += __shfl_xor_sync(0xffffffffu, s, o);
        const float inv = 1.f / s;
        sc[l] = e0 * inv; sc[l + 32] = e1 * inv;
    }
    __syncthreads();

    float acc = 0.f, sm = 0.f, sq = 0.f;
#pragma unroll 8
    for (int n = 0; n < Nn; n++) {
        const float v = base[n * H1n + tid];
        acc += sc[n] * v;
        sm += v;
        sq += v * v;
    }
    x1[b * H1n + tid] = acc;

    red[tid] = sm; __syncthreads();
    for (int s = 128; s > 0; s >>= 1) { if (tid < s) red[tid] += red[tid + s]; __syncthreads(); }
    const float S = red[0]; __syncthreads();
    red[tid] = sq; __syncthreads();
    for (int s = 128; s > 0; s >>= 1) { if (tid < s) red[tid] += red[tid + s]; __syncthreads(); }
    const float SQ = red[0]; __syncthreads();
    red[tid] = acc; __syncthreads();
    for (int s = 128; s > 0; s >>= 1) { if (tid < s) red[tid] += red[tid + s]; __syncthreads(); }
    const float SX = red[0]; __syncthreads();
    red[tid] = acc * acc; __syncthreads();
    for (int s = 128; s > 0; s >>= 1) { if (tid < s) red[tid] += red[tid + s]; __syncthreads(); }
    const float SXQ = red[0];

    if (tid == 0) {
        const float inv_cnt = 1.f / (float)(Nn * H1n);
        const float mean = S * inv_cnt;
        const float var  = SQ * inv_cnt - mean * mean;
        mb[b] = mean;
        rb[b] = rsqrtf(fmaxf(var, 0.f) + BN_EPS);
        px[b]  = SX;
        pxq[b] = SXQ;
    }
}

// ---------------------------------------------------------------------------
// Attention layer 2 (H=128). One block per node, 128 threads.
// ---------------------------------------------------------------------------
__global__ void attn2_k(const float* __restrict__ nbh, const float* __restrict__ xh,
                        const float* __restrict__ a_self, const float* __restrict__ a_nb,
                        float* __restrict__ x2, float* __restrict__ px,
                        float* __restrict__ pxq)
{
    const int b = blockIdx.x, tid = threadIdx.x;
    __shared__ float red[128];
    __shared__ float sc[64];

    const float* base = nbh + (size_t)b * Nn * H2n;

    red[tid] = xh[b * H2n + tid] * a_self[tid];
    __syncthreads();
    for (int s = 64; s > 0; s >>= 1) { if (tid < s) red[tid] += red[tid + s]; __syncthreads(); }
    const float sx = red[0];
    __syncthreads();

    const int w = tid >> 5, l = tid & 31;
#pragma unroll
    for (int nn = 0; nn < 16; nn++) {
        const int n = w * 16 + nn;
        const float* row = base + n * H2n;
        float acc = 0.f;
#pragma unroll
        for (int j = 0; j < 4; j++) acc += row[l + 32 * j] * a_nb[l + 32 * j];
#pragma unroll
        for (int o = 16; o > 0; o >>= 1) acc += __shfl_down_sync(0xffffffffu, acc, o);
        if (l == 0) sc[n] = sx + acc;
    }
    __syncthreads();

    if (w == 0) {
        float v0 = sc[l], v1 = sc[l + 32];
        v0 = v0 > 0.f ? v0 : ALPHA_LRELU * v0;
        v1 = v1 > 0.f ? v1 : ALPHA_LRELU * v1;
        float mx = fmaxf(v0, v1);
#pragma unroll
        for (int o = 16; o > 0; o >>= 1) mx = fmaxf(mx, __shfl_xor_sync(0xffffffffu, mx, o));
        float e0 = __expf(v0 - mx), e1 = __expf(v1 - mx);
        float s = e0 + e1;
#pragma unroll
        for (int o = 16; o > 0; o >>= 1) s += __shfl_xor_sync(0xffffffffu, s, o);
        const float inv = 1.f / s;
        sc[l] = e0 * inv; sc[l + 32] = e1 * inv;
    }
    __syncthreads();

    float acc = 0.f;
#pragma unroll 8
    for (int n = 0; n < Nn; n++) acc += sc[n] * base[n * H2n + tid];
    x2[b * H2n + tid] = acc;

    red[tid] = acc; __syncthreads();
    for (int s = 64; s > 0; s >>= 1) { if (tid < s) red[tid] += red[tid + s]; __syncthreads(); }
    const float SX = red[0]; __syncthreads();
    red[tid] = acc * acc; __syncthreads();
    for (int s = 64; s > 0; s >>= 1) { if (tid < s) red[tid] += red[tid + s]; __syncthreads(); }
    const float SXQ = red[0];

    if (tid == 0) { px[b] = SX; pxq[b] = SXQ; }
}

// ---------------------------------------------------------------------------
// Finalize global BN stats from per-block partials (1 block, 1024 threads).
// ---------------------------------------------------------------------------
__global__ void bnstats_k(const float* __restrict__ px, const float* __restrict__ pxq,
                          float* __restrict__ bn, float invcnt)
{
    __shared__ float r1[1024];
    __shared__ float r2[1024];
    const int t = threadIdx.x;
    r1[t] = px[t]; r2[t] = pxq[t];
    __syncthreads();
    for (int s = 512; s > 0; s >>= 1) {
        if (t < s) { r1[t] += r1[t + s]; r2[t] += r2[t + s]; }
        __syncthreads();
    }
    if (t == 0) {
        const float mean = r1[0] * invcnt;
        const float var  = r2[0] * invcnt - mean * mean;
        bn[0] = mean;
        bn[1] = rsqrtf(fmaxf(var, 0.f) + BN_EPS);
    }
}

// ---------------------------------------------------------------------------
// Final: BN-ReLU x2 + logits. One block per b, 128 threads.
// ---------------------------------------------------------------------------
__global__ void logits_k(const float* __restrict__ x2, const float* __restrict__ bn2,
                         const float* __restrict__ gptr, const float* __restrict__ beptr,
                         const float* __restrict__ Wl, const float* __restrict__ bl,
                         float* __restrict__ out)
{
    const int b = blockIdx.x, t = threadIdx.x;
    __shared__ float xn[H2n];
    const float m = bn2[0], r = bn2[1], g = gptr[0], be = beptr[0];
    float v = x2[b * H2n + t];
    xn[t] = fmaxf(g * (v - m) * r + be, 0.f);
    __syncthreads();

    const float* wr = Wl + t * H2n;
    float acc = bl[t];
#pragma unroll 8
    for (int h = 0; h < H2n; h++) acc += xn[h] * wr[h];
    out[b * NCn + t] = acc;
}

// ---------------------------------------------------------------------------
// Launch
// ---------------------------------------------------------------------------
extern "C" void kernel_launch(void* const* d_in, const int* in_sizes, int n_in,
                              void* d_out, int out_size)
{
    (void)in_sizes; (void)n_in; (void)out_size;
    const float* x   = (const float*)d_in[0];
    const float* nb  = (const float*)d_in[1];
    const float* W1  = (const float*)d_in[2];
    const float* b1  = (const float*)d_in[3];
    const float* a11 = (const float*)d_in[4];
    const float* a12 = (const float*)d_in[5];
    const float* g1  = (const float*)d_in[6];
    const float* be1 = (const float*)d_in[7];
    const float* W2  = (const float*)d_in[8];
    const float* b2  = (const float*)d_in[9];
    const float* a21 = (const float*)d_in[10];
    const float* a22 = (const float*)d_in[11];
    const float* g2  = (const float*)d_in[12];
    const float* be2 = (const float*)d_in[13];
    const float* Wl  = (const float*)d_in[14];
    const float* bl  = (const float*)d_in[15];
    float* out = (float*)d_out;

    float *nbh1, *xh1, *x1, *mb1, *rb1, *px1, *pxq1, *bn1;
    float *nbh2, *xh2, *x2, *px2, *pxq2, *bn2;
    __nv_bfloat16 *w1hi, *w1lo, *w2hi, *w2lo;
    cudaGetSymbolAddress((void**)&nbh1, g_nbh1);
    cudaGetSymbolAddress((void**)&xh1,  g_xh1);
    cudaGetSymbolAddress((void**)&x1,   g_x1);
    cudaGetSymbolAddress((void**)&mb1,  g_mb1);
    cudaGetSymbolAddress((void**)&rb1,  g_rb1);
    cudaGetSymbolAddress((void**)&px1,  g_px1);
    cudaGetSymbolAddress((void**)&pxq1, g_pxq1);
    cudaGetSymbolAddress((void**)&bn1,  g_bn1);
    cudaGetSymbolAddress((void**)&nbh2, g_nbh2);
    cudaGetSymbolAddress((void**)&xh2,  g_xh2);
    cudaGetSymbolAddress((void**)&x2,   g_x2);
    cudaGetSymbolAddress((void**)&px2,  g_px2);
    cudaGetSymbolAddress((void**)&pxq2, g_pxq2);
    cudaGetSymbolAddress((void**)&bn2,  g_bn2);
    cudaGetSymbolAddress((void**)&w1hi, g_w1hi);
    cudaGetSymbolAddress((void**)&w1lo, g_w1lo);
    cudaGetSymbolAddress((void**)&w2hi, g_w2hi);
    cudaGetSymbolAddress((void**)&w2lo, g_w2lo);

    // dynamic smem opt-in (idempotent; not a stream op)
    cudaFuncSetAttribute(tc_gemm1_k, cudaFuncAttributeMaxDynamicSharedMemorySize, G1_SMEM);
    cudaFuncSetAttribute(tc_gemm2_k, cudaFuncAttributeMaxDynamicSharedMemorySize, G2_SMEM);

    // W -> bf16 hi/lo splits
    wsplit_k<<<(H1n * Fn) / 1024, 1024>>>(W1, w1hi, w1lo, H1n * Fn);
    wsplit_k<<<(H2n * H1n) / 1024, 1024>>>(W2, w2hi, w2lo, H2n * H1n);

    // Layer 1 GEMMs (mma.sync, pipelined): sign(input) @ (Whi+Wlo)^T + b1
    tc_gemm1_k<<<dim3(Mn / 128, H1n / 128), 256, G1_SMEM>>>(nb, w1hi, w1lo, b1, nbh1, Fn, H1n);
    tc_gemm1_k<<<dim3(Bn / 128, H1n / 128), 256, G1_SMEM>>>(x,  w1hi, w1lo, b1, xh1, Fn, H1n);

    // Attention 1 + per-node neighbor BN stats + x1 partial stats
    attn1_k<<<Bn, 256>>>(nbh1, xh1, a11, a12, x1, mb1, rb1, px1, pxq1);
    bnstats_k<<<1, 1024>>>(px1, pxq1, bn1, 1.f / (float)(Bn * H1n));

    // Layer 2 GEMMs (mma.sync, split both operands): BN-ReLU(input) @ W2^T + b2
    tc_gemm2_k<<<Mn / 128, 256, G2_SMEM>>>(nbh1, w2hi, w2lo, b2, nbh2,
                                           mb1, rb1, Nn, g1, be1);
    tc_gemm2_k<<<Bn / 128, 256, G2_SMEM>>>(x1, w2hi, w2lo, b2, xh2,
                                           bn1, bn1 + 1, 1 << 30, g1, be1);
    // Attention 2 + x2 partial stats
    attn2_k<<<Bn, 128>>>(nbh2, xh2, a21, a22, x2, px2, pxq2);
    bnstats_k<<<1, 1024>>>(px2, pxq2, bn2, 1.f / (float)(Bn * H2n));

    // BN-ReLU + classifier
    logits_k<<<Bn, 128>>>(x2, bn2, g2, be2, Wl, bl, out);
}

// round 6
// speedup vs baseline: 2.6164x; 1.2372x over previous
#include <cuda_runtime.h>
#include <cuda_bf16.h>
#include <cstdint>
#include <cstddef>

// Problem dims (fixed by the dataset)
#define Bn   1024
#define Nn   64
#define Fn   1024
#define H1n  256
#define H2n  128
#define NCn  128
#define Mn   (Bn*Nn)      // 65536
#define ALPHA_LRELU 0.2f
#define BN_EPS 1e-5f

// ---------------------------------------------------------------------------
// Scratch (static device globals — allocation-free, per harness rules)
// ---------------------------------------------------------------------------
__device__ float g_nbh1[(size_t)Mn * H1n];   // 64 MB
__device__ float g_xh1 [Bn * H1n];
__device__ float g_x1  [Bn * H1n];
__device__ float g_mb1 [Bn];
__device__ float g_rb1 [Bn];
__device__ float g_px1 [Bn];
__device__ float g_pxq1[Bn];
__device__ float g_bn1 [2];
__device__ float g_nbh2[(size_t)Mn * H2n];   // 32 MB
__device__ float g_xh2 [Bn * H2n];
__device__ float g_x2  [Bn * H2n];
__device__ float g_px2 [Bn];
__device__ float g_pxq2[Bn];
__device__ float g_bn2 [2];
__device__ __nv_bfloat16 g_w1hi[H1n * Fn];   // 512 KB
__device__ __nv_bfloat16 g_w1lo[H1n * Fn];   // 512 KB
__device__ __nv_bfloat16 g_w2hi[H2n * H1n];  // 64 KB
__device__ __nv_bfloat16 g_w2lo[H2n * H1n];  // 64 KB

// ---------------------------------------------------------------------------
// PTX helpers: ldmatrix + mma.sync + cp.async (arch-stable)
// ---------------------------------------------------------------------------
__device__ __forceinline__ uint32_t smem_u32(const void* p) {
    uint32_t a;
    asm("{ .reg .u64 t; cvta.to.shared.u64 t, %1; cvt.u32.u64 %0, t; }" : "=r"(a) : "l"(p));
    return a;
}
__device__ __forceinline__ void ldsm_x4(uint32_t* r, uint32_t addr) {
    asm volatile("ldmatrix.sync.aligned.m8n8.x4.shared.b16 {%0,%1,%2,%3}, [%4];"
                 : "=r"(r[0]), "=r"(r[1]), "=r"(r[2]), "=r"(r[3]) : "r"(addr));
}
__device__ __forceinline__ void mma16816(float* c, const uint32_t* a, const uint32_t* b) {
    asm volatile("mma.sync.aligned.m16n8k16.row.col.f32.bf16.bf16.f32 "
                 "{%0,%1,%2,%3}, {%4,%5,%6,%7}, {%8,%9}, {%0,%1,%2,%3};"
                 : "+f"(c[0]), "+f"(c[1]), "+f"(c[2]), "+f"(c[3])
                 : "r"(a[0]), "r"(a[1]), "r"(a[2]), "r"(a[3]), "r"(b[0]), "r"(b[1]));
}
__device__ __forceinline__ void cp16(uint32_t dst, const void* src) {
    asm volatile("cp.async.cg.shared.global [%0], [%1], 16;" :: "r"(dst), "l"(src) : "memory");
}
#define CP_COMMIT() asm volatile("cp.async.commit_group;" ::: "memory")
#define CP_WAIT1()  asm volatile("cp.async.wait_group 1;" ::: "memory")

__device__ __forceinline__ uint32_t swz128(uint32_t off) { return off ^ ((off >> 3) & 0x70); }

__device__ __forceinline__ uint32_t pack_sign_bf16x2(float a, float b) {
    float sa = (fabsf(a) >= 1e-12f) ? copysignf(1.f, a) : a * 1e12f;
    float sb = (fabsf(b) >= 1e-12f) ? copysignf(1.f, b) : b * 1e12f;
    __nv_bfloat162 h = __floats2bfloat162_rn(sa, sb);
    return *reinterpret_cast<uint32_t*>(&h);
}
__device__ __forceinline__ uint32_t pack_bf16x2(float a, float b) {
    __nv_bfloat162 h = __floats2bfloat162_rn(a, b);
    return *reinterpret_cast<uint32_t*>(&h);
}

// ---------------------------------------------------------------------------
// W split: Whi = bf16(W), Wlo = bf16(W - Whi)
// ---------------------------------------------------------------------------
__global__ void wsplit_k(const float* __restrict__ W, __nv_bfloat16* __restrict__ hi,
                         __nv_bfloat16* __restrict__ lo, int n)
{
    int i = blockIdx.x * blockDim.x + threadIdx.x;
    if (i < n) {
        float w = W[i];
        __nv_bfloat16 h = __float2bfloat16_rn(w);
        hi[i] = h;
        lo[i] = __float2bfloat16_rn(w - __bfloat162float(h));
    }
}

// ---------------------------------------------------------------------------
// GEMM1 (merged nb+x): C[.,256] = sign(A[.,1024]) @ W1^T + b1.
// blockIdx.x < 512 -> rows of nb -> nbh1; else rows of x -> xh1.
// CTA tile 128x128, K-chunk 64, 8 warps, 2 CTAs/SM (regs<=128).
// SMEM: [A0 16K][A1 16K][Bh0][Bh1][Bl0][Bl1] = 96KB, cp.async 2-deep for B.
// ---------------------------------------------------------------------------
#define G1_SMEM (6 * 16384)

__global__ __launch_bounds__(256, 2)
void tc_gemm1_k(const float* __restrict__ Anb, const float* __restrict__ Ax,
                const __nv_bfloat16* __restrict__ Whi, const __nv_bfloat16* __restrict__ Wlo,
                const float* __restrict__ bias,
                float* __restrict__ Cnb, float* __restrict__ Cx)
{
    extern __shared__ char smem[];
    const uint32_t sb = smem_u32(smem);
    const int K = Fn;

    const int tid = threadIdx.x;
    const int wid = tid >> 5, lane = tid & 31;
    const int bx = blockIdx.x;
    const int n0 = blockIdx.y * 128;

    const float* Abase;  float* Cbase;  int m0;
    if (bx < Mn / 128) { Abase = Anb; Cbase = Cnb; m0 = bx * 128; }
    else               { Abase = Ax;  Cbase = Cx;  m0 = (bx - Mn / 128) * 128; }

    const int mrow0 = (wid >> 1) * 32;
    const int ncol0 = (wid & 1) * 64;

    const int r  = tid >> 1;
    const int c0 = (tid & 1) * 32;
    const float* aSrc = Abase + (size_t)(m0 + r) * K + c0;
    const __nv_bfloat16* hSrc = Whi + (size_t)(n0 + r) * K + c0;
    const __nv_bfloat16* lSrc = Wlo + (size_t)(n0 + r) * K + c0;

    uint32_t sOff[4];
#pragma unroll
    for (int j = 0; j < 4; j++)
        sOff[j] = swz128((uint32_t)(r * 128 + (c0 + j * 8) * 2));

    float acc[2][8][4];
#pragma unroll
    for (int i = 0; i < 2; i++)
#pragma unroll
        for (int g = 0; g < 8; g++)
#pragma unroll
            for (int q = 0; q < 4; q++) acc[i][g][q] = 0.f;

    const int aRow[2] = { mrow0 + (lane & 15), mrow0 + 16 + (lane & 15) };
    const int aKof   = (lane >> 4) << 3;
    const int bRowBase = ncol0 + (lane & 7) + ((lane >> 4) << 3);
    const int bKof   = ((lane >> 3) & 1) << 3;

    // ---- prologue: 2-deep cp.async pipeline for B tiles ----
#pragma unroll
    for (int j = 0; j < 4; j++) {
        cp16(sb + 32768 + sOff[j], hSrc + j * 8);
        cp16(sb + 65536 + sOff[j], lSrc + j * 8);
    }
    CP_COMMIT();
#pragma unroll
    for (int j = 0; j < 4; j++) {
        cp16(sb + 32768 + 16384 + sOff[j], hSrc + 64 + j * 8);
        cp16(sb + 65536 + 16384 + sOff[j], lSrc + 64 + j * 8);
    }
    CP_COMMIT();

    const int nCh = K / 64;   // 16
    for (int ch = 0; ch < nCh; ch++) {
        const int buf = ch & 1;
        const uint32_t aB  = sb + buf * 16384;
        const uint32_t bhB = sb + 32768 + buf * 16384;
        const uint32_t blB = sb + 65536 + buf * 16384;
        const int k0 = ch * 64;

        // A: LDG fp32 -> sign-pack bf16 -> swizzled STS (overlaps cp wait)
#pragma unroll
        for (int j = 0; j < 4; j++) {
            float4 f0 = *(const float4*)(aSrc + k0 + j * 8);
            float4 f1 = *(const float4*)(aSrc + k0 + j * 8 + 4);
            uint4 o;
            o.x = pack_sign_bf16x2(f0.x, f0.y);
            o.y = pack_sign_bf16x2(f0.z, f0.w);
            o.z = pack_sign_bf16x2(f1.x, f1.y);
            o.w = pack_sign_bf16x2(f1.z, f1.w);
            *(uint4*)(smem + buf * 16384 + sOff[j]) = o;
        }
        CP_WAIT1();        // this buf's B group done; next buf's may stay in flight
        __syncthreads();

        // consume: separate hi/lo fragment arrays for ILP
#pragma unroll
        for (int ks = 0; ks < 4; ks++) {
            uint32_t af[2][4], bfh[4][4], bfl[4][4];
#pragma unroll
            for (int mi = 0; mi < 2; mi++)
                ldsm_x4(af[mi], aB + swz128((uint32_t)(aRow[mi] * 128 + (ks * 16 + aKof) * 2)));
#pragma unroll
            for (int q = 0; q < 4; q++) {
                const uint32_t ro = swz128((uint32_t)((bRowBase + q * 16) * 128 +
                                                      (ks * 16 + bKof) * 2));
                ldsm_x4(bfh[q], bhB + ro);
                ldsm_x4(bfl[q], blB + ro);
            }
#pragma unroll
            for (int mi = 0; mi < 2; mi++)
#pragma unroll
                for (int g = 0; g < 8; g++)
                    mma16816(acc[mi][g], af[mi], &bfh[g >> 1][(g & 1) * 2]);
#pragma unroll
            for (int mi = 0; mi < 2; mi++)
#pragma unroll
                for (int g = 0; g < 8; g++)
                    mma16816(acc[mi][g], af[mi], &bfl[g >> 1][(g & 1) * 2]);
        }
        __syncthreads();

        // refill this buf with chunk ch+2's B tiles
        if (ch + 2 < nCh) {
            const int k2 = (ch + 2) * 64;
#pragma unroll
            for (int j = 0; j < 4; j++) {
                cp16(bhB + sOff[j], hSrc + k2 + j * 8);
                cp16(blB + sOff[j], lSrc + k2 + j * 8);
            }
            CP_COMMIT();
        }
    }

    // ---- epilogue: bias add + fp32 store ----
#pragma unroll
    for (int mi = 0; mi < 2; mi++) {
        const int row = m0 + mrow0 + mi * 16 + (lane >> 2);
#pragma unroll
        for (int g = 0; g < 8; g++) {
            const int col = n0 + ncol0 + g * 8 + (lane & 3) * 2;
            const float b0 = bias[col], b1 = bias[col + 1];
            *(float2*)(Cbase + (size_t)row * H1n + col) =
                make_float2(acc[mi][g][0] + b0, acc[mi][g][1] + b1);
            *(float2*)(Cbase + (size_t)(row + 8) * H1n + col) =
                make_float2(acc[mi][g][2] + b0, acc[mi][g][3] + b1);
        }
    }
}

// ---------------------------------------------------------------------------
// GEMM2 (merged): C[.,128] = BN_ReLU(A[.,256]) @ W2^T + b2.
// blockIdx.x < 512 -> rows of nbh1 (per-node stats) -> nbh2; else x1 (global
// stats) -> xh2. A split hi/lo in producer; C = Ahi*Whi + Alo*Whi + Ahi*Wlo.
// SMEM: [Ahi 16K][Alo 16K][Bhi 16K][Blo 16K] = 64KB, 2 CTAs/SM.
// ---------------------------------------------------------------------------
#define G2_SMEM (4 * 16384)

__global__ __launch_bounds__(256, 2)
void tc_gemm2_k(const float* __restrict__ Anb, const float* __restrict__ Ax,
                const __nv_bfloat16* __restrict__ Whi, const __nv_bfloat16* __restrict__ Wlo,
                const float* __restrict__ bias,
                float* __restrict__ Cnb, float* __restrict__ Cx,
                const float* __restrict__ mb, const float* __restrict__ rb,
                const float* __restrict__ bn,
                const float* __restrict__ gptr, const float* __restrict__ beptr)
{
    extern __shared__ char smem[];
    const uint32_t sb = smem_u32(smem);
    const uint32_t ahB = sb, alB = sb + 16384, bhB = sb + 32768, blB = sb + 49152;

    const int tid = threadIdx.x;
    const int wid = tid >> 5, lane = tid & 31;
    const int bx = blockIdx.x;

    const int r  = tid >> 1;
    const int c0 = (tid & 1) * 32;

    const float* Abase;  float* Cbase;  int m0;
    float rm, rr;
    if (bx < Mn / 128) {
        Abase = Anb; Cbase = Cnb; m0 = bx * 128;
        rm = mb[(m0 + r) / Nn]; rr = rb[(m0 + r) / Nn];
    } else {
        Abase = Ax; Cbase = Cx; m0 = (bx - Mn / 128) * 128;
        rm = bn[0]; rr = bn[1];
    }
    const float gg = *gptr, bb = *beptr;

    const int mrow0 = (wid >> 1) * 32;
    const int ncol0 = (wid & 1) * 64;

    const float* aSrc = Abase + (size_t)(m0 + r) * H1n + c0;
    const __nv_bfloat16* hSrc = Whi + (size_t)r * H1n + c0;
    const __nv_bfloat16* lSrc = Wlo + (size_t)r * H1n + c0;

    uint32_t sOff[4];
#pragma unroll
    for (int j = 0; j < 4; j++)
        sOff[j] = swz128((uint32_t)(r * 128 + (c0 + j * 8) * 2));

    float acc[2][8][4];
#pragma unroll
    for (int i = 0; i < 2; i++)
#pragma unroll
        for (int g = 0; g < 8; g++)
#pragma unroll
            for (int q = 0; q < 4; q++) acc[i][g][q] = 0.f;

    const int aRow[2] = { mrow0 + (lane & 15), mrow0 + 16 + (lane & 15) };
    const int aKof   = (lane >> 4) << 3;
    const int bRowBase = ncol0 + (lane & 7) + ((lane >> 4) << 3);
    const int bKof   = ((lane >> 3) & 1) << 3;

    for (int k0 = 0; k0 < H1n; k0 += 64) {
        // producers: BN-ReLU + hi/lo split for A, raw copies for W2
#pragma unroll
        for (int j = 0; j < 4; j++) {
            float4 f0 = *(const float4*)(aSrc + k0 + j * 8);
            float4 f1 = *(const float4*)(aSrc + k0 + j * 8 + 4);
            float v[8] = {f0.x, f0.y, f0.z, f0.w, f1.x, f1.y, f1.z, f1.w};
            float hi[8], lo[8];
#pragma unroll
            for (int e = 0; e < 8; e++) {
                float t = fmaxf(gg * (v[e] - rm) * rr + bb, 0.f);
                __nv_bfloat16 h = __float2bfloat16_rn(t);
                hi[e] = __bfloat162float(h);
                lo[e] = t - hi[e];
            }
            uint4 oh, ol;
            oh.x = pack_bf16x2(hi[0], hi[1]); oh.y = pack_bf16x2(hi[2], hi[3]);
            oh.z = pack_bf16x2(hi[4], hi[5]); oh.w = pack_bf16x2(hi[6], hi[7]);
            ol.x = pack_bf16x2(lo[0], lo[1]); ol.y = pack_bf16x2(lo[2], lo[3]);
            ol.z = pack_bf16x2(lo[4], lo[5]); ol.w = pack_bf16x2(lo[6], lo[7]);
            *(uint4*)(smem + sOff[j]) = oh;
            *(uint4*)(smem + 16384 + sOff[j]) = ol;
            uint4 vh = *(const uint4*)(hSrc + k0 + j * 8);
            uint4 vl = *(const uint4*)(lSrc + k0 + j * 8);
            *(uint4*)(smem + 32768 + sOff[j]) = vh;
            *(uint4*)(smem + 49152 + sOff[j]) = vl;
        }
        __syncthreads();

        // consumers
#pragma unroll
        for (int ks = 0; ks < 4; ks++) {
            uint32_t ah[2][4], al[2][4], bf_[4][4];
#pragma unroll
            for (int mi = 0; mi < 2; mi++) {
                const uint32_t ro = swz128((uint32_t)(aRow[mi] * 128 + (ks * 16 + aKof) * 2));
                ldsm_x4(ah[mi], ahB + ro);
                ldsm_x4(al[mi], alB + ro);
            }
#pragma unroll
            for (int q = 0; q < 4; q++)
                ldsm_x4(bf_[q], bhB + swz128((uint32_t)((bRowBase + q * 16) * 128 +
                                                        (ks * 16 + bKof) * 2)));
#pragma unroll
            for (int mi = 0; mi < 2; mi++)
#pragma unroll
                for (int g = 0; g < 8; g++) {
                    mma16816(acc[mi][g], ah[mi], &bf_[g >> 1][(g & 1) * 2]);
                    mma16816(acc[mi][g], al[mi], &bf_[g >> 1][(g & 1) * 2]);
                }
#pragma unroll
            for (int q = 0; q < 4; q++)
                ldsm_x4(bf_[q], blB + swz128((uint32_t)((bRowBase + q * 16) * 128 +
                                                        (ks * 16 + bKof) * 2)));
#pragma unroll
            for (int mi = 0; mi < 2; mi++)
#pragma unroll
                for (int g = 0; g < 8; g++)
                    mma16816(acc[mi][g], ah[mi], &bf_[g >> 1][(g & 1) * 2]);
        }
        __syncthreads();
    }

    // epilogue
#pragma unroll
    for (int mi = 0; mi < 2; mi++) {
        const int row = m0 + mrow0 + mi * 16 + (lane >> 2);
#pragma unroll
        for (int g = 0; g < 8; g++) {
            const int col = ncol0 + g * 8 + (lane & 3) * 2;
            const float b0 = bias[col], b1 = bias[col + 1];
            *(float2*)(Cbase + (size_t)row * H2n + col) =
                make_float2(acc[mi][g][0] + b0, acc[mi][g][1] + b1);
            *(float2*)(Cbase + (size_t)(row + 8) * H2n + col) =
                make_float2(acc[mi][g][2] + b0, acc[mi][g][3] + b1);
        }
    }
}

// ---------------------------------------------------------------------------
// Attention layer 1 (H=256). One block per graph node b, 256 threads.
// ---------------------------------------------------------------------------
__global__ void attn1_k(const float* __restrict__ nbh, const float* __restrict__ xh,
                        const float* __restrict__ a_self, const float* __restrict__ a_nb,
                        float* __restrict__ x1, float* __restrict__ mb,
                        float* __restrict__ rb, float* __restrict__ px,
                        float* __restrict__ pxq)
{
    const int b = blockIdx.x, tid = threadIdx.x;
    __shared__ float red[256];
    __shared__ float sc[64];

    const float* base = nbh + (size_t)b * Nn * H1n;

    red[tid] = xh[b * H1n + tid] * a_self[tid];
    __syncthreads();
    for (int s = 128; s > 0; s >>= 1) {
        if (tid < s) red[tid] += red[tid + s];
        __syncthreads();
    }
    const float sx = red[0];
    __syncthreads();

    const int w = tid >> 5, l = tid & 31;
#pragma unroll
    for (int nn = 0; nn < 8; nn++) {
        const int n = w * 8 + nn;
        const float* row = base + n * H1n;
        float acc = 0.f;
#pragma unroll
        for (int j = 0; j < 8; j++) acc += row[l + 32 * j] * a_nb[l + 32 * j];
#pragma unroll
        for (int o = 16; o > 0; o >>= 1) acc += __shfl_down_sync(0xffffffffu, acc, o);
        if (l == 0) sc[n] = sx + acc;
    }
    __syncthreads();

    if (w == 0) {
        float v0 = sc[l], v1 = sc[l + 32];
        v0 = v0 > 0.f ? v0 : ALPHA_LRELU * v0;
        v1 = v1 > 0.f ? v1 : ALPHA_LRELU * v1;
        float mx = fmaxf(v0, v1);
#pragma unroll
        for (int o = 16; o > 0; o >>= 1) mx = fmaxf(mx, __shfl_xor_sync(0xffffffffu, mx, o));
        float e0 = __expf(v0 - mx), e1 = __expf(v1 - mx);
        float s = e0 + e1;
#pragma unroll
        for (int o = 16; o > 0; o >>= 1) s += __shfl_xor_sync(0xffffffffu, s, o);
        const float inv = 1.f / s;
        sc[l] = e0 * inv; sc[l + 32] = e1 * inv;
    }
    __syncthreads();

    float acc = 0.f, sm = 0.f, sq = 0.f;
#pragma unroll 8
    for (int n = 0; n < Nn; n++) {
        const float v = base[n * H1n + tid];
        acc += sc[n] * v;
        sm += v;
        sq += v * v;
    }
    x1[b * H1n + tid] = acc;

    red[tid] = sm; __syncthreads();
    for (int s = 128; s > 0; s >>= 1) { if (tid < s) red[tid] += red[tid + s]; __syncthreads(); }
    const float S = red[0]; __syncthreads();
    red[tid] = sq; __syncthreads();
    for (int s = 128; s > 0; s >>= 1) { if (tid < s) red[tid] += red[tid + s]; __syncthreads(); }
    const float SQ = red[0]; __syncthreads();
    red[tid] = acc; __syncthreads();
    for (int s = 128; s > 0; s >>= 1) { if (tid < s) red[tid] += red[tid + s]; __syncthreads(); }
    const float SX = red[0]; __syncthreads();
    red[tid] = acc * acc; __syncthreads();
    for (int s = 128; s > 0; s >>= 1) { if (tid < s) red[tid] += red[tid + s]; __syncthreads(); }
    const float SXQ = red[0];

    if (tid == 0) {
        const float inv_cnt = 1.f / (float)(Nn * H1n);
        const float mean = S * inv_cnt;
        const float var  = SQ * inv_cnt - mean * mean;
        mb[b] = mean;
        rb[b] = rsqrtf(fmaxf(var, 0.f) + BN_EPS);
        px[b]  = SX;
        pxq[b] = SXQ;
    }
}

// ---------------------------------------------------------------------------
// Attention layer 2 (H=128). One block per node, 128 threads.
// ---------------------------------------------------------------------------
__global__ void attn2_k(const float* __restrict__ nbh, const float* __restrict__ xh,
                        const float* __restrict__ a_self, const float* __restrict__ a_nb,
                        float* __restrict__ x2, float* __restrict__ px,
                        float* __restrict__ pxq)
{
    const int b = blockIdx.x, tid = threadIdx.x;
    __shared__ float red[128];
    __shared__ float sc[64];

    const float* base = nbh + (size_t)b * Nn * H2n;

    red[tid] = xh[b * H2n + tid] * a_self[tid];
    __syncthreads();
    for (int s = 64; s > 0; s >>= 1) { if (tid < s) red[tid] += red[tid + s]; __syncthreads(); }
    const float sx = red[0];
    __syncthreads();

    const int w = tid >> 5, l = tid & 31;
#pragma unroll
    for (int nn = 0; nn < 16; nn++) {
        const int n = w * 16 + nn;
        const float* row = base + n * H2n;
        float acc = 0.f;
#pragma unroll
        for (int j = 0; j < 4; j++) acc += row[l + 32 * j] * a_nb[l + 32 * j];
#pragma unroll
        for (int o = 16; o > 0; o >>= 1) acc += __shfl_down_sync(0xffffffffu, acc, o);
        if (l == 0) sc[n] = sx + acc;
    }
    __syncthreads();

    if (w == 0) {
        float v0 = sc[l], v1 = sc[l + 32];
        v0 = v0 > 0.f ? v0 : ALPHA_LRELU * v0;
        v1 = v1 > 0.f ? v1 : ALPHA_LRELU * v1;
        float mx = fmaxf(v0, v1);
#pragma unroll
        for (int o = 16; o > 0; o >>= 1) mx = fmaxf(mx, __shfl_xor_sync(0xffffffffu, mx, o));
        float e0 = __expf(v0 - mx), e1 = __expf(v1 - mx);
        float s = e0 + e1;
#pragma unroll
        for (int o = 16; o > 0; o >>= 1) s += __shfl_xor_sync(0xffffffffu, s, o);
        const float inv = 1.f / s;
        sc[l] = e0 * inv; sc[l + 32] = e1 * inv;
    }
    __syncthreads();

    float acc = 0.f;
#pragma unroll 8
    for (int n = 0; n < Nn; n++) acc += sc[n] * base[n * H2n + tid];
    x2[b * H2n + tid] = acc;

    red[tid] = acc; __syncthreads();
    for (int s = 64; s > 0; s >>= 1) { if (tid < s) red[tid] += red[tid + s]; __syncthreads(); }
    const float SX = red[0]; __syncthreads();
    red[tid] = acc * acc; __syncthreads();
    for (int s = 64; s > 0; s >>= 1) { if (tid < s) red[tid] += red[tid + s]; __syncthreads(); }
    const float SXQ = red[0];

    if (tid == 0) { px[b] = SX; pxq[b] = SXQ; }
}

// ---------------------------------------------------------------------------
// Finalize global BN stats from per-block partials (1 block, 1024 threads).
// ---------------------------------------------------------------------------
__global__ void bnstats_k(const float* __restrict__ px, const float* __restrict__ pxq,
                          float* __restrict__ bn, float invcnt)
{
    __shared__ float r1[1024];
    __shared__ float r2[1024];
    const int t = threadIdx.x;
    r1[t] = px[t]; r2[t] = pxq[t];
    __syncthreads();
    for (int s = 512; s > 0; s >>= 1) {
        if (t < s) { r1[t] += r1[t + s]; r2[t] += r2[t + s]; }
        __syncthreads();
    }
    if (t == 0) {
        const float mean = r1[0] * invcnt;
        const float var  = r2[0] * invcnt - mean * mean;
        bn[0] = mean;
        bn[1] = rsqrtf(fmaxf(var, 0.f) + BN_EPS);
    }
}

// ---------------------------------------------------------------------------
// Final: BN-ReLU x2 + logits. One block per b, 128 threads.
// ---------------------------------------------------------------------------
__global__ void logits_k(const float* __restrict__ x2, const float* __restrict__ bn2,
                         const float* __restrict__ gptr, const float* __restrict__ beptr,
                         const float* __restrict__ Wl, const float* __restrict__ bl,
                         float* __restrict__ out)
{
    const int b = blockIdx.x, t = threadIdx.x;
    __shared__ float xn[H2n];
    const float m = bn2[0], r = bn2[1], g = gptr[0], be = beptr[0];
    float v = x2[b * H2n + t];
    xn[t] = fmaxf(g * (v - m) * r + be, 0.f);
    __syncthreads();

    const float* wr = Wl + t * H2n;
    float acc = bl[t];
#pragma unroll 8
    for (int h = 0; h < H2n; h++) acc += xn[h] * wr[h];
    out[b * NCn + t] = acc;
}

// ---------------------------------------------------------------------------
// Launch
// ---------------------------------------------------------------------------
extern "C" void kernel_launch(void* const* d_in, const int* in_sizes, int n_in,
                              void* d_out, int out_size)
{
    (void)in_sizes; (void)n_in; (void)out_size;
    const float* x   = (const float*)d_in[0];
    const float* nb  = (const float*)d_in[1];
    const float* W1  = (const float*)d_in[2];
    const float* b1  = (const float*)d_in[3];
    const float* a11 = (const float*)d_in[4];
    const float* a12 = (const float*)d_in[5];
    const float* g1  = (const float*)d_in[6];
    const float* be1 = (const float*)d_in[7];
    const float* W2  = (const float*)d_in[8];
    const float* b2  = (const float*)d_in[9];
    const float* a21 = (const float*)d_in[10];
    const float* a22 = (const float*)d_in[11];
    const float* g2  = (const float*)d_in[12];
    const float* be2 = (const float*)d_in[13];
    const float* Wl  = (const float*)d_in[14];
    const float* bl  = (const float*)d_in[15];
    float* out = (float*)d_out;

    float *nbh1, *xh1, *x1, *mb1, *rb1, *px1, *pxq1, *bn1;
    float *nbh2, *xh2, *x2, *px2, *pxq2, *bn2;
    __nv_bfloat16 *w1hi, *w1lo, *w2hi, *w2lo;
    cudaGetSymbolAddress((void**)&nbh1, g_nbh1);
    cudaGetSymbolAddress((void**)&xh1,  g_xh1);
    cudaGetSymbolAddress((void**)&x1,   g_x1);
    cudaGetSymbolAddress((void**)&mb1,  g_mb1);
    cudaGetSymbolAddress((void**)&rb1,  g_rb1);
    cudaGetSymbolAddress((void**)&px1,  g_px1);
    cudaGetSymbolAddress((void**)&pxq1, g_pxq1);
    cudaGetSymbolAddress((void**)&bn1,  g_bn1);
    cudaGetSymbolAddress((void**)&nbh2, g_nbh2);
    cudaGetSymbolAddress((void**)&xh2,  g_xh2);
    cudaGetSymbolAddress((void**)&x2,   g_x2);
    cudaGetSymbolAddress((void**)&px2,  g_px2);
    cudaGetSymbolAddress((void**)&pxq2, g_pxq2);
    cudaGetSymbolAddress((void**)&bn2,  g_bn2);
    cudaGetSymbolAddress((void**)&w1hi, g_w1hi);
    cudaGetSymbolAddress((void**)&w1lo, g_w1lo);
    cudaGetSymbolAddress((void**)&w2hi, g_w2hi);
    cudaGetSymbolAddress((void**)&w2lo, g_w2lo);

    cudaFuncSetAttribute(tc_gemm1_k, cudaFuncAttributeMaxDynamicSharedMemorySize, G1_SMEM);
    cudaFuncSetAttribute(tc_gemm2_k, cudaFuncAttributeMaxDynamicSharedMemorySize, G2_SMEM);

    // W -> bf16 hi/lo splits
    wsplit_k<<<(H1n * Fn) / 1024, 1024>>>(W1, w1hi, w1lo, H1n * Fn);
    wsplit_k<<<(H2n * H1n) / 1024, 1024>>>(W2, w2hi, w2lo, H2n * H1n);

    // Layer 1 GEMM (merged nb + x): sign(input) @ (Whi+Wlo)^T + b1
    tc_gemm1_k<<<dim3(Mn / 128 + Bn / 128, H1n / 128), 256, G1_SMEM>>>(
        nb, x, w1hi, w1lo, b1, nbh1, xh1);

    // Attention 1 + per-node neighbor BN stats + x1 partial stats
    attn1_k<<<Bn, 256>>>(nbh1, xh1, a11, a12, x1, mb1, rb1, px1, pxq1);
    bnstats_k<<<1, 1024>>>(px1, pxq1, bn1, 1.f / (float)(Bn * H1n));

    // Layer 2 GEMM (merged): BN-ReLU(input) @ W2^T + b2
    tc_gemm2_k<<<Mn / 128 + Bn / 128, 256, G2_SMEM>>>(
        nbh1, x1, w2hi, w2lo, b2, nbh2, xh2, mb1, rb1, bn1, g1, be1);

    // Attention 2 + x2 partial stats
    attn2_k<<<Bn, 128>>>(nbh2, xh2, a21, a22, x2, px2, pxq2);
    bnstats_k<<<1, 1024>>>(px2, pxq2, bn2, 1.f / (float)(Bn * H2n));

    // BN-ReLU + classifier
    logits_k<<<Bn, 128>>>(x2, bn2, g2, be2, Wl, bl, out);
}

// round 7
// speedup vs baseline: 2.8864x; 1.1032x over previous
#include <cuda_runtime.h>
#include <cuda_bf16.h>
#include <cuda_fp16.h>
#include <cstdint>
#include <cstddef>

// Problem dims (fixed by the dataset)
#define Bn   1024
#define Nn   64
#define Fn   1024
#define H1n  256
#define H2n  128
#define NCn  128
#define Mn   (Bn*Nn)      // 65536
#define ALPHA_LRELU 0.2f
#define BN_EPS 1e-5f

// ---------------------------------------------------------------------------
// Scratch (static device globals — allocation-free, per harness rules)
// ---------------------------------------------------------------------------
__device__ float g_nbh1[(size_t)Mn * H1n];   // 64 MB
__device__ float g_xh1 [Bn * H1n];
__device__ float g_x1  [Bn * H1n];
__device__ float g_mb1 [Bn];
__device__ float g_rb1 [Bn];
__device__ float g_px1 [Bn];
__device__ float g_pxq1[Bn];
__device__ float g_bn1 [2];
__device__ float g_nbh2[(size_t)Mn * H2n];   // 32 MB
__device__ float g_xh2 [Bn * H2n];
__device__ float g_x2  [Bn * H2n];
__device__ float g_px2 [Bn];
__device__ float g_pxq2[Bn];
__device__ float g_bn2 [2];
__device__ __half        g_w1h [H1n * Fn];   // 512 KB (fp16 single)
__device__ __nv_bfloat16 g_w2hi[H2n * H1n];  // 64 KB
__device__ __nv_bfloat16 g_w2lo[H2n * H1n];  // 64 KB

// ---------------------------------------------------------------------------
// PTX helpers: ldmatrix + mma.sync + cp.async (arch-stable)
// ---------------------------------------------------------------------------
__device__ __forceinline__ uint32_t smem_u32(const void* p) {
    uint32_t a;
    asm("{ .reg .u64 t; cvta.to.shared.u64 t, %1; cvt.u32.u64 %0, t; }" : "=r"(a) : "l"(p));
    return a;
}
__device__ __forceinline__ void ldsm_x4(uint32_t* r, uint32_t addr) {
    asm volatile("ldmatrix.sync.aligned.m8n8.x4.shared.b16 {%0,%1,%2,%3}, [%4];"
                 : "=r"(r[0]), "=r"(r[1]), "=r"(r[2]), "=r"(r[3]) : "r"(addr));
}
__device__ __forceinline__ void mma16816_bf16(float* c, const uint32_t* a, const uint32_t* b) {
    asm volatile("mma.sync.aligned.m16n8k16.row.col.f32.bf16.bf16.f32 "
                 "{%0,%1,%2,%3}, {%4,%5,%6,%7}, {%8,%9}, {%0,%1,%2,%3};"
                 : "+f"(c[0]), "+f"(c[1]), "+f"(c[2]), "+f"(c[3])
                 : "r"(a[0]), "r"(a[1]), "r"(a[2]), "r"(a[3]), "r"(b[0]), "r"(b[1]));
}
__device__ __forceinline__ void mma16816_f16(float* c, const uint32_t* a, const uint32_t* b) {
    asm volatile("mma.sync.aligned.m16n8k16.row.col.f32.f16.f16.f32 "
                 "{%0,%1,%2,%3}, {%4,%5,%6,%7}, {%8,%9}, {%0,%1,%2,%3};"
                 : "+f"(c[0]), "+f"(c[1]), "+f"(c[2]), "+f"(c[3])
                 : "r"(a[0]), "r"(a[1]), "r"(a[2]), "r"(a[3]), "r"(b[0]), "r"(b[1]));
}
__device__ __forceinline__ void cp16(uint32_t dst, const void* src) {
    asm volatile("cp.async.cg.shared.global [%0], [%1], 16;" :: "r"(dst), "l"(src) : "memory");
}
#define CP_COMMIT() asm volatile("cp.async.commit_group;" ::: "memory")
#define CP_WAIT1()  asm volatile("cp.async.wait_group 1;" ::: "memory")

__device__ __forceinline__ uint32_t swz128(uint32_t off) { return off ^ ((off >> 3) & 0x70); }

__device__ __forceinline__ uint32_t pack_sign_half2(float a, float b) {
    float sa = (fabsf(a) >= 1e-12f) ? copysignf(1.f, a) : a * 1e12f;
    float sb = (fabsf(b) >= 1e-12f) ? copysignf(1.f, b) : b * 1e12f;
    __half2 h = __floats2half2_rn(sa, sb);
    return *reinterpret_cast<uint32_t*>(&h);
}
__device__ __forceinline__ uint32_t pack_bf16x2(float a, float b) {
    __nv_bfloat162 h = __floats2bfloat162_rn(a, b);
    return *reinterpret_cast<uint32_t*>(&h);
}

// ---------------------------------------------------------------------------
// W1 -> fp16 single;  W2 -> bf16 hi/lo split
// ---------------------------------------------------------------------------
__global__ void whalf_k(const float* __restrict__ W, __half* __restrict__ h, int n)
{
    int i = blockIdx.x * blockDim.x + threadIdx.x;
    if (i < n) h[i] = __float2half_rn(W[i]);
}
__global__ void wsplit_k(const float* __restrict__ W, __nv_bfloat16* __restrict__ hi,
                         __nv_bfloat16* __restrict__ lo, int n)
{
    int i = blockIdx.x * blockDim.x + threadIdx.x;
    if (i < n) {
        float w = W[i];
        __nv_bfloat16 h = __float2bfloat16_rn(w);
        hi[i] = h;
        lo[i] = __float2bfloat16_rn(w - __bfloat162float(h));
    }
}

// ---------------------------------------------------------------------------
// GEMM1 (merged nb+x, fp16 single-pass): C[.,256] = sign(A[.,1024]) @ W1^T + b1.
// A is exactly +-1 (fp16-exact); W1 in fp16 (2^-11 rounding -> ~3e-4 rel).
// CTA tile 128x128, K-chunk 64, 8 warps, 2 CTAs/SM.
// SMEM: [A0 16K][A1 16K][B0 16K][B1 16K] = 64KB. cp.async 2-deep for B.
// ---------------------------------------------------------------------------
#define G1_SMEM (4 * 16384)

__global__ __launch_bounds__(256, 2)
void tc_gemm1_k(const float* __restrict__ Anb, const float* __restrict__ Ax,
                const __half* __restrict__ Wh, const float* __restrict__ bias,
                float* __restrict__ Cnb, float* __restrict__ Cx)
{
    extern __shared__ char smem[];
    const uint32_t sb = smem_u32(smem);
    const int K = Fn;

    const int tid = threadIdx.x;
    const int wid = tid >> 5, lane = tid & 31;
    const int bx = blockIdx.x;
    const int n0 = blockIdx.y * 128;

    const float* Abase;  float* Cbase;  int m0;
    if (bx < Mn / 128) { Abase = Anb; Cbase = Cnb; m0 = bx * 128; }
    else               { Abase = Ax;  Cbase = Cx;  m0 = (bx - Mn / 128) * 128; }

    const int mrow0 = (wid >> 1) * 32;
    const int ncol0 = (wid & 1) * 64;

    const int r  = tid >> 1;
    const int c0 = (tid & 1) * 32;
    const float* aSrc = Abase + (size_t)(m0 + r) * K + c0;
    const __half* hSrc = Wh + (size_t)(n0 + r) * K + c0;

    uint32_t sOff[4];
#pragma unroll
    for (int j = 0; j < 4; j++)
        sOff[j] = swz128((uint32_t)(r * 128 + (c0 + j * 8) * 2));

    float acc[2][8][4];
#pragma unroll
    for (int i = 0; i < 2; i++)
#pragma unroll
        for (int g = 0; g < 8; g++)
#pragma unroll
            for (int q = 0; q < 4; q++) acc[i][g][q] = 0.f;

    const int aRow[2] = { mrow0 + (lane & 15), mrow0 + 16 + (lane & 15) };
    const int aKof   = (lane >> 4) << 3;
    const int bRowBase = ncol0 + (lane & 7) + ((lane >> 4) << 3);
    const int bKof   = ((lane >> 3) & 1) << 3;

    // ---- prologue: 2-deep cp.async pipeline for B tiles ----
#pragma unroll
    for (int j = 0; j < 4; j++) cp16(sb + 32768 + sOff[j], hSrc + j * 8);
    CP_COMMIT();
#pragma unroll
    for (int j = 0; j < 4; j++) cp16(sb + 32768 + 16384 + sOff[j], hSrc + 64 + j * 8);
    CP_COMMIT();

    const int nCh = K / 64;   // 16
    for (int ch = 0; ch < nCh; ch++) {
        const int buf = ch & 1;
        const uint32_t aB = sb + buf * 16384;
        const uint32_t bB = sb + 32768 + buf * 16384;
        const int k0 = ch * 64;

        // A: LDG fp32 -> sign-pack fp16 -> swizzled STS
#pragma unroll
        for (int j = 0; j < 4; j++) {
            float4 f0 = *(const float4*)(aSrc + k0 + j * 8);
            float4 f1 = *(const float4*)(aSrc + k0 + j * 8 + 4);
            uint4 o;
            o.x = pack_sign_half2(f0.x, f0.y);
            o.y = pack_sign_half2(f0.z, f0.w);
            o.z = pack_sign_half2(f1.x, f1.y);
            o.w = pack_sign_half2(f1.z, f1.w);
            *(uint4*)(smem + buf * 16384 + sOff[j]) = o;
        }
        CP_WAIT1();
        __syncthreads();

#pragma unroll
        for (int ks = 0; ks < 4; ks++) {
            uint32_t af[2][4], bf_[4][4];
#pragma unroll
            for (int mi = 0; mi < 2; mi++)
                ldsm_x4(af[mi], aB + swz128((uint32_t)(aRow[mi] * 128 + (ks * 16 + aKof) * 2)));
#pragma unroll
            for (int q = 0; q < 4; q++)
                ldsm_x4(bf_[q], bB + swz128((uint32_t)((bRowBase + q * 16) * 128 +
                                                       (ks * 16 + bKof) * 2)));
#pragma unroll
            for (int mi = 0; mi < 2; mi++)
#pragma unroll
                for (int g = 0; g < 8; g++)
                    mma16816_f16(acc[mi][g], af[mi], &bf_[g >> 1][(g & 1) * 2]);
        }
        __syncthreads();

        // refill this buf with chunk ch+2's B tile
        if (ch + 2 < nCh) {
            const int k2 = (ch + 2) * 64;
#pragma unroll
            for (int j = 0; j < 4; j++) cp16(bB + sOff[j], hSrc + k2 + j * 8);
            CP_COMMIT();
        }
    }

    // ---- epilogue: bias add + fp32 store ----
#pragma unroll
    for (int mi = 0; mi < 2; mi++) {
        const int row = m0 + mrow0 + mi * 16 + (lane >> 2);
#pragma unroll
        for (int g = 0; g < 8; g++) {
            const int col = n0 + ncol0 + g * 8 + (lane & 3) * 2;
            const float b0 = bias[col], b1 = bias[col + 1];
            *(float2*)(Cbase + (size_t)row * H1n + col) =
                make_float2(acc[mi][g][0] + b0, acc[mi][g][1] + b1);
            *(float2*)(Cbase + (size_t)(row + 8) * H1n + col) =
                make_float2(acc[mi][g][2] + b0, acc[mi][g][3] + b1);
        }
    }
}

// ---------------------------------------------------------------------------
// GEMM2 (merged, bf16 3-pass): C[.,128] = BN_ReLU(A[.,256]) @ W2^T + b2.
// C = Ahi*Whi + Alo*Whi + Ahi*Wlo. SMEM 64KB, 2 CTAs/SM.
// ---------------------------------------------------------------------------
#define G2_SMEM (4 * 16384)

__global__ __launch_bounds__(256, 2)
void tc_gemm2_k(const float* __restrict__ Anb, const float* __restrict__ Ax,
                const __nv_bfloat16* __restrict__ Whi, const __nv_bfloat16* __restrict__ Wlo,
                const float* __restrict__ bias,
                float* __restrict__ Cnb, float* __restrict__ Cx,
                const float* __restrict__ mb, const float* __restrict__ rb,
                const float* __restrict__ bn,
                const float* __restrict__ gptr, const float* __restrict__ beptr)
{
    extern __shared__ char smem[];
    const uint32_t sb = smem_u32(smem);
    const uint32_t ahB = sb, alB = sb + 16384, bhB = sb + 32768, blB = sb + 49152;

    const int tid = threadIdx.x;
    const int wid = tid >> 5, lane = tid & 31;
    const int bx = blockIdx.x;

    const int r  = tid >> 1;
    const int c0 = (tid & 1) * 32;

    const float* Abase;  float* Cbase;  int m0;
    float rm, rr;
    if (bx < Mn / 128) {
        Abase = Anb; Cbase = Cnb; m0 = bx * 128;
        rm = mb[(m0 + r) / Nn]; rr = rb[(m0 + r) / Nn];
    } else {
        Abase = Ax; Cbase = Cx; m0 = (bx - Mn / 128) * 128;
        rm = bn[0]; rr = bn[1];
    }
    const float gg = *gptr, bb = *beptr;

    const int mrow0 = (wid >> 1) * 32;
    const int ncol0 = (wid & 1) * 64;

    const float* aSrc = Abase + (size_t)(m0 + r) * H1n + c0;
    const __nv_bfloat16* hSrc = Whi + (size_t)r * H1n + c0;
    const __nv_bfloat16* lSrc = Wlo + (size_t)r * H1n + c0;

    uint32_t sOff[4];
#pragma unroll
    for (int j = 0; j < 4; j++)
        sOff[j] = swz128((uint32_t)(r * 128 + (c0 + j * 8) * 2));

    float acc[2][8][4];
#pragma unroll
    for (int i = 0; i < 2; i++)
#pragma unroll
        for (int g = 0; g < 8; g++)
#pragma unroll
            for (int q = 0; q < 4; q++) acc[i][g][q] = 0.f;

    const int aRow[2] = { mrow0 + (lane & 15), mrow0 + 16 + (lane & 15) };
    const int aKof   = (lane >> 4) << 3;
    const int bRowBase = ncol0 + (lane & 7) + ((lane >> 4) << 3);
    const int bKof   = ((lane >> 3) & 1) << 3;

    for (int k0 = 0; k0 < H1n; k0 += 64) {
#pragma unroll
        for (int j = 0; j < 4; j++) {
            float4 f0 = *(const float4*)(aSrc + k0 + j * 8);
            float4 f1 = *(const float4*)(aSrc + k0 + j * 8 + 4);
            float v[8] = {f0.x, f0.y, f0.z, f0.w, f1.x, f1.y, f1.z, f1.w};
            float hi[8], lo[8];
#pragma unroll
            for (int e = 0; e < 8; e++) {
                float t = fmaxf(gg * (v[e] - rm) * rr + bb, 0.f);
                __nv_bfloat16 h = __float2bfloat16_rn(t);
                hi[e] = __bfloat162float(h);
                lo[e] = t - hi[e];
            }
            uint4 oh, ol;
            oh.x = pack_bf16x2(hi[0], hi[1]); oh.y = pack_bf16x2(hi[2], hi[3]);
            oh.z = pack_bf16x2(hi[4], hi[5]); oh.w = pack_bf16x2(hi[6], hi[7]);
            ol.x = pack_bf16x2(lo[0], lo[1]); ol.y = pack_bf16x2(lo[2], lo[3]);
            ol.z = pack_bf16x2(lo[4], lo[5]); ol.w = pack_bf16x2(lo[6], lo[7]);
            *(uint4*)(smem + sOff[j]) = oh;
            *(uint4*)(smem + 16384 + sOff[j]) = ol;
            uint4 vh = *(const uint4*)(hSrc + k0 + j * 8);
            uint4 vl = *(const uint4*)(lSrc + k0 + j * 8);
            *(uint4*)(smem + 32768 + sOff[j]) = vh;
            *(uint4*)(smem + 49152 + sOff[j]) = vl;
        }
        __syncthreads();

#pragma unroll
        for (int ks = 0; ks < 4; ks++) {
            uint32_t ah[2][4], al[2][4], bf_[4][4];
#pragma unroll
            for (int mi = 0; mi < 2; mi++) {
                const uint32_t ro = swz128((uint32_t)(aRow[mi] * 128 + (ks * 16 + aKof) * 2));
                ldsm_x4(ah[mi], ahB + ro);
                ldsm_x4(al[mi], alB + ro);
            }
#pragma unroll
            for (int q = 0; q < 4; q++)
                ldsm_x4(bf_[q], bhB + swz128((uint32_t)((bRowBase + q * 16) * 128 +
                                                        (ks * 16 + bKof) * 2)));
#pragma unroll
            for (int mi = 0; mi < 2; mi++)
#pragma unroll
                for (int g = 0; g < 8; g++) {
                    mma16816_bf16(acc[mi][g], ah[mi], &bf_[g >> 1][(g & 1) * 2]);
                    mma16816_bf16(acc[mi][g], al[mi], &bf_[g >> 1][(g & 1) * 2]);
                }
#pragma unroll
            for (int q = 0; q < 4; q++)
                ldsm_x4(bf_[q], blB + swz128((uint32_t)((bRowBase + q * 16) * 128 +
                                                        (ks * 16 + bKof) * 2)));
#pragma unroll
            for (int mi = 0; mi < 2; mi++)
#pragma unroll
                for (int g = 0; g < 8; g++)
                    mma16816_bf16(acc[mi][g], ah[mi], &bf_[g >> 1][(g & 1) * 2]);
        }
        __syncthreads();
    }

#pragma unroll
    for (int mi = 0; mi < 2; mi++) {
        const int row = m0 + mrow0 + mi * 16 + (lane >> 2);
#pragma unroll
        for (int g = 0; g < 8; g++) {
            const int col = ncol0 + g * 8 + (lane & 3) * 2;
            const float b0 = bias[col], b1 = bias[col + 1];
            *(float2*)(Cbase + (size_t)row * H2n + col) =
                make_float2(acc[mi][g][0] + b0, acc[mi][g][1] + b1);
            *(float2*)(Cbase + (size_t)(row + 8) * H2n + col) =
                make_float2(acc[mi][g][2] + b0, acc[mi][g][3] + b1);
        }
    }
}

// ---------------------------------------------------------------------------
// Attention layer 1 (H=256). One block per node, 256 threads.
// nbh tile (64x256 = 64KB) cached in dynamic smem during the score pass;
// the weighted-sum pass reads smem instead of DRAM (halves traffic).
// ---------------------------------------------------------------------------
#define A1_SMEM (Nn * H1n * 4)

__global__ void attn1_k(const float* __restrict__ nbh, const float* __restrict__ xh,
                        const float* __restrict__ a_self, const float* __restrict__ a_nb,
                        float* __restrict__ x1, float* __restrict__ mb,
                        float* __restrict__ rb, float* __restrict__ px,
                        float* __restrict__ pxq)
{
    extern __shared__ float tile[];   // [64][256]
    const int b = blockIdx.x, tid = threadIdx.x;
    __shared__ float red[256];
    __shared__ float sc[64];

    const float* base = nbh + (size_t)b * Nn * H1n;

    red[tid] = xh[b * H1n + tid] * a_self[tid];
    __syncthreads();
    for (int s = 128; s > 0; s >>= 1) {
        if (tid < s) red[tid] += red[tid + s];
        __syncthreads();
    }
    const float sx = red[0];
    __syncthreads();

    const int w = tid >> 5, l = tid & 31;
#pragma unroll
    for (int nn = 0; nn < 8; nn++) {
        const int n = w * 8 + nn;
        const float* row = base + n * H1n;
        float acc = 0.f;
#pragma unroll
        for (int j = 0; j < 8; j++) {
            const float v = row[l + 32 * j];
            tile[n * H1n + l + 32 * j] = v;
            acc += v * a_nb[l + 32 * j];
        }
#pragma unroll
        for (int o = 16; o > 0; o >>= 1) acc += __shfl_down_sync(0xffffffffu, acc, o);
        if (l == 0) sc[n] = sx + acc;
    }
    __syncthreads();

    if (w == 0) {
        float v0 = sc[l], v1 = sc[l + 32];
        v0 = v0 > 0.f ? v0 : ALPHA_LRELU * v0;
        v1 = v1 > 0.f ? v1 : ALPHA_LRELU * v1;
        float mx = fmaxf(v0, v1);
#pragma unroll
        for (int o = 16; o > 0; o >>= 1) mx = fmaxf(mx, __shfl_xor_sync(0xffffffffu, mx, o));
        float e0 = __expf(v0 - mx), e1 = __expf(v1 - mx);
        float s = e0 + e1;
#pragma unroll
        for (int o = 16; o > 0; o >>= 1) s += __shfl_xor_sync(0xffffffffu, s, o);
        const float inv = 1.f / s;
        sc[l] = e0 * inv; sc[l + 32] = e1 * inv;
    }
    __syncthreads();

    float acc = 0.f, sm = 0.f, sq = 0.f;
#pragma unroll 8
    for (int n = 0; n < Nn; n++) {
        const float v = tile[n * H1n + tid];
        acc += sc[n] * v;
        sm += v;
        sq += v * v;
    }
    x1[b * H1n + tid] = acc;

    red[tid] = sm; __syncthreads();
    for (int s = 128; s > 0; s >>= 1) { if (tid < s) red[tid] += red[tid + s]; __syncthreads(); }
    const float S = red[0]; __syncthreads();
    red[tid] = sq; __syncthreads();
    for (int s = 128; s > 0; s >>= 1) { if (tid < s) red[tid] += red[tid + s]; __syncthreads(); }
    const float SQ = red[0]; __syncthreads();
    red[tid] = acc; __syncthreads();
    for (int s = 128; s > 0; s >>= 1) { if (tid < s) red[tid] += red[tid + s]; __syncthreads(); }
    const float SX = red[0]; __syncthreads();
    red[tid] = acc * acc; __syncthreads();
    for (int s = 128; s > 0; s >>= 1) { if (tid < s) red[tid] += red[tid + s]; __syncthreads(); }
    const float SXQ = red[0];

    if (tid == 0) {
        const float inv_cnt = 1.f / (float)(Nn * H1n);
        const float mean = S * inv_cnt;
        const float var  = SQ * inv_cnt - mean * mean;
        mb[b] = mean;
        rb[b] = rsqrtf(fmaxf(var, 0.f) + BN_EPS);
        px[b]  = SX;
        pxq[b] = SXQ;
    }
}

// ---------------------------------------------------------------------------
// Attention layer 2 (H=128). One block per node, 128 threads.
// ---------------------------------------------------------------------------
__global__ void attn2_k(const float* __restrict__ nbh, const float* __restrict__ xh,
                        const float* __restrict__ a_self, const float* __restrict__ a_nb,
                        float* __restrict__ x2, float* __restrict__ px,
                        float* __restrict__ pxq)
{
    const int b = blockIdx.x, tid = threadIdx.x;
    __shared__ float red[128];
    __shared__ float sc[64];

    const float* base = nbh + (size_t)b * Nn * H2n;

    red[tid] = xh[b * H2n + tid] * a_self[tid];
    __syncthreads();
    for (int s = 64; s > 0; s >>= 1) { if (tid < s) red[tid] += red[tid + s]; __syncthreads(); }
    const float sx = red[0];
    __syncthreads();

    const int w = tid >> 5, l = tid & 31;
#pragma unroll
    for (int nn = 0; nn < 16; nn++) {
        const int n = w * 16 + nn;
        const float* row = base + n * H2n;
        float acc = 0.f;
#pragma unroll
        for (int j = 0; j < 4; j++) acc += row[l + 32 * j] * a_nb[l + 32 * j];
#pragma unroll
        for (int o = 16; o > 0; o >>= 1) acc += __shfl_down_sync(0xffffffffu, acc, o);
        if (l == 0) sc[n] = sx + acc;
    }
    __syncthreads();

    if (w == 0) {
        float v0 = sc[l], v1 = sc[l + 32];
        v0 = v0 > 0.f ? v0 : ALPHA_LRELU * v0;
        v1 = v1 > 0.f ? v1 : ALPHA_LRELU * v1;
        float mx = fmaxf(v0, v1);
#pragma unroll
        for (int o = 16; o > 0; o >>= 1) mx = fmaxf(mx, __shfl_xor_sync(0xffffffffu, mx, o));
        float e0 = __expf(v0 - mx), e1 = __expf(v1 - mx);
        float s = e0 + e1;
#pragma unroll
        for (int o = 16; o > 0; o >>= 1) s += __shfl_xor_sync(0xffffffffu, s, o);
        const float inv = 1.f / s;
        sc[l] = e0 * inv; sc[l + 32] = e1 * inv;
    }
    __syncthreads();

    float acc = 0.f;
#pragma unroll 8
    for (int n = 0; n < Nn; n++) acc += sc[n] * base[n * H2n + tid];
    x2[b * H2n + tid] = acc;

    red[tid] = acc; __syncthreads();
    for (int s = 64; s > 0; s >>= 1) { if (tid < s) red[tid] += red[tid + s]; __syncthreads(); }
    const float SX = red[0]; __syncthreads();
    red[tid] = acc * acc; __syncthreads();
    for (int s = 64; s > 0; s >>= 1) { if (tid < s) red[tid] += red[tid + s]; __syncthreads(); }
    const float SXQ = red[0];

    if (tid == 0) { px[b] = SX; pxq[b] = SXQ; }
}

// ---------------------------------------------------------------------------
// Finalize global BN stats from per-block partials (1 block, 1024 threads).
// ---------------------------------------------------------------------------
__global__ void bnstats_k(const float* __restrict__ px, const float* __restrict__ pxq,
                          float* __restrict__ bn, float invcnt)
{
    __shared__ float r1[1024];
    __shared__ float r2[1024];
    const int t = threadIdx.x;
    r1[t] = px[t]; r2[t] = pxq[t];
    __syncthreads();
    for (int s = 512; s > 0; s >>= 1) {
        if (t < s) { r1[t] += r1[t + s]; r2[t] += r2[t + s]; }
        __syncthreads();
    }
    if (t == 0) {
        const float mean = r1[0] * invcnt;
        const float var  = r2[0] * invcnt - mean * mean;
        bn[0] = mean;
        bn[1] = rsqrtf(fmaxf(var, 0.f) + BN_EPS);
    }
}

// ---------------------------------------------------------------------------
// Final: BN-ReLU x2 + logits. One block per b, 128 threads.
// ---------------------------------------------------------------------------
__global__ void logits_k(const float* __restrict__ x2, const float* __restrict__ bn2,
                         const float* __restrict__ gptr, const float* __restrict__ beptr,
                         const float* __restrict__ Wl, const float* __restrict__ bl,
                         float* __restrict__ out)
{
    const int b = blockIdx.x, t = threadIdx.x;
    __shared__ float xn[H2n];
    const float m = bn2[0], r = bn2[1], g = gptr[0], be = beptr[0];
    float v = x2[b * H2n + t];
    xn[t] = fmaxf(g * (v - m) * r + be, 0.f);
    __syncthreads();

    const float* wr = Wl + t * H2n;
    float acc = bl[t];
#pragma unroll 8
    for (int h = 0; h < H2n; h++) acc += xn[h] * wr[h];
    out[b * NCn + t] = acc;
}

// ---------------------------------------------------------------------------
// Launch
// ---------------------------------------------------------------------------
extern "C" void kernel_launch(void* const* d_in, const int* in_sizes, int n_in,
                              void* d_out, int out_size)
{
    (void)in_sizes; (void)n_in; (void)out_size;
    const float* x   = (const float*)d_in[0];
    const float* nb  = (const float*)d_in[1];
    const float* W1  = (const float*)d_in[2];
    const float* b1  = (const float*)d_in[3];
    const float* a11 = (const float*)d_in[4];
    const float* a12 = (const float*)d_in[5];
    const float* g1  = (const float*)d_in[6];
    const float* be1 = (const float*)d_in[7];
    const float* W2  = (const float*)d_in[8];
    const float* b2  = (const float*)d_in[9];
    const float* a21 = (const float*)d_in[10];
    const float* a22 = (const float*)d_in[11];
    const float* g2  = (const float*)d_in[12];
    const float* be2 = (const float*)d_in[13];
    const float* Wl  = (const float*)d_in[14];
    const float* bl  = (const float*)d_in[15];
    float* out = (float*)d_out;

    float *nbh1, *xh1, *x1, *mb1, *rb1, *px1, *pxq1, *bn1;
    float *nbh2, *xh2, *x2, *px2, *pxq2, *bn2;
    __half *w1h;
    __nv_bfloat16 *w2hi, *w2lo;
    cudaGetSymbolAddress((void**)&nbh1, g_nbh1);
    cudaGetSymbolAddress((void**)&xh1,  g_xh1);
    cudaGetSymbolAddress((void**)&x1,   g_x1);
    cudaGetSymbolAddress((void**)&mb1,  g_mb1);
    cudaGetSymbolAddress((void**)&rb1,  g_rb1);
    cudaGetSymbolAddress((void**)&px1,  g_px1);
    cudaGetSymbolAddress((void**)&pxq1, g_pxq1);
    cudaGetSymbolAddress((void**)&bn1,  g_bn1);
    cudaGetSymbolAddress((void**)&nbh2, g_nbh2);
    cudaGetSymbolAddress((void**)&xh2,  g_xh2);
    cudaGetSymbolAddress((void**)&x2,   g_x2);
    cudaGetSymbolAddress((void**)&px2,  g_px2);
    cudaGetSymbolAddress((void**)&pxq2, g_pxq2);
    cudaGetSymbolAddress((void**)&bn2,  g_bn2);
    cudaGetSymbolAddress((void**)&w1h,  g_w1h);
    cudaGetSymbolAddress((void**)&w2hi, g_w2hi);
    cudaGetSymbolAddress((void**)&w2lo, g_w2lo);

    cudaFuncSetAttribute(tc_gemm1_k, cudaFuncAttributeMaxDynamicSharedMemorySize, G1_SMEM);
    cudaFuncSetAttribute(tc_gemm2_k, cudaFuncAttributeMaxDynamicSharedMemorySize, G2_SMEM);
    cudaFuncSetAttribute(attn1_k,   cudaFuncAttributeMaxDynamicSharedMemorySize, A1_SMEM);

    // Weight conversions
    whalf_k<<<(H1n * Fn) / 1024, 1024>>>(W1, w1h, H1n * Fn);
    wsplit_k<<<(H2n * H1n) / 1024, 1024>>>(W2, w2hi, w2lo, H2n * H1n);

    // Layer 1 GEMM (merged nb + x, fp16 single-pass)
    tc_gemm1_k<<<dim3(Mn / 128 + Bn / 128, H1n / 128), 256, G1_SMEM>>>(
        nb, x, w1h, b1, nbh1, xh1);

    // Attention 1 + per-node neighbor BN stats + x1 partial stats
    attn1_k<<<Bn, 256, A1_SMEM>>>(nbh1, xh1, a11, a12, x1, mb1, rb1, px1, pxq1);
    bnstats_k<<<1, 1024>>>(px1, pxq1, bn1, 1.f / (float)(Bn * H1n));

    // Layer 2 GEMM (merged, bf16 3-pass)
    tc_gemm2_k<<<Mn / 128 + Bn / 128, 256, G2_SMEM>>>(
        nbh1, x1, w2hi, w2lo, b2, nbh2, xh2, mb1, rb1, bn1, g1, be1);

    // Attention 2 + x2 partial stats
    attn2_k<<<Bn, 128>>>(nbh2, xh2, a21, a22, x2, px2, pxq2);
    bnstats_k<<<1, 1024>>>(px2, pxq2, bn2, 1.f / (float)(Bn * H2n));

    // BN-ReLU + classifier
    logits_k<<<Bn, 128>>>(x2, bn2, g2, be2, Wl, bl, out);
}

// round 10
// speedup vs baseline: 3.1303x; 1.0845x over previous
#include <cuda_runtime.h>
#include <cuda_bf16.h>
#include <cuda_fp16.h>
#include <cstdint>
#include <cstddef>

// Problem dims (fixed by the dataset)
#define Bn   1024
#define Nn   64
#define Fn   1024
#define H1n  256
#define H2n  128
#define NCn  128
#define Mn   (Bn*Nn)      // 65536
#define ALPHA_LRELU 0.2f
#define BN_EPS 1e-5f

// ---------------------------------------------------------------------------
// Scratch (static device globals — allocation-free, per harness rules)
// ---------------------------------------------------------------------------
__device__ float g_nbh1[(size_t)Mn * H1n];   // 64 MB
__device__ float g_xh1 [Bn * H1n];
__device__ float g_x1  [Bn * H1n];
__device__ float g_mb1 [Bn];
__device__ float g_rb1 [Bn];
__device__ float g_px1 [Bn];
__device__ float g_pxq1[Bn];
__device__ float g_bn1 [2];
__device__ float g_nbh2[(size_t)Mn * H2n];   // 32 MB
__device__ float g_xh2 [Bn * H2n];
__device__ float g_x2  [Bn * H2n];
__device__ float g_px2 [Bn];
__device__ float g_pxq2[Bn];
__device__ float g_bn2 [2];
__device__ __half g_w1h[H1n * Fn];   // 512 KB (fp16)
__device__ __half g_w2h[H2n * H1n];  // 64 KB  (fp16)

// ---------------------------------------------------------------------------
// PTX helpers: ldmatrix + mma.sync + cp.async (arch-stable)
// ---------------------------------------------------------------------------
__device__ __forceinline__ uint32_t smem_u32(const void* p) {
    uint32_t a;
    asm("{ .reg .u64 t; cvta.to.shared.u64 t, %1; cvt.u32.u64 %0, t; }" : "=r"(a) : "l"(p));
    return a;
}
__device__ __forceinline__ void ldsm_x4(uint32_t* r, uint32_t addr) {
    asm volatile("ldmatrix.sync.aligned.m8n8.x4.shared.b16 {%0,%1,%2,%3}, [%4];"
                 : "=r"(r[0]), "=r"(r[1]), "=r"(r[2]), "=r"(r[3]) : "r"(addr));
}
__device__ __forceinline__ void mma16816_f16(float* c, const uint32_t* a, const uint32_t* b) {
    asm volatile("mma.sync.aligned.m16n8k16.row.col.f32.f16.f16.f32 "
                 "{%0,%1,%2,%3}, {%4,%5,%6,%7}, {%8,%9}, {%0,%1,%2,%3};"
                 : "+f"(c[0]), "+f"(c[1]), "+f"(c[2]), "+f"(c[3])
                 : "r"(a[0]), "r"(a[1]), "r"(a[2]), "r"(a[3]), "r"(b[0]), "r"(b[1]));
}
__device__ __forceinline__ void cp16(uint32_t dst, const void* src) {
    asm volatile("cp.async.cg.shared.global [%0], [%1], 16;" :: "r"(dst), "l"(src) : "memory");
}
#define CP_COMMIT() asm volatile("cp.async.commit_group;" ::: "memory")
#define CP_WAIT0()  asm volatile("cp.async.wait_group 0;" ::: "memory")
#define CP_WAIT1()  asm volatile("cp.async.wait_group 1;" ::: "memory")

__device__ __forceinline__ uint32_t swz128(uint32_t off) { return off ^ ((off >> 3) & 0x70); }

__device__ __forceinline__ uint32_t pack_sign_half2(float a, float b) {
    float sa = (fabsf(a) >= 1e-12f) ? copysignf(1.f, a) : a * 1e12f;
    float sb = (fabsf(b) >= 1e-12f) ? copysignf(1.f, b) : b * 1e12f;
    __half2 h = __floats2half2_rn(sa, sb);
    return *reinterpret_cast<uint32_t*>(&h);
}
__device__ __forceinline__ uint32_t pack_half2(float a, float b) {
    __half2 h = __floats2half2_rn(a, b);
    return *reinterpret_cast<uint32_t*>(&h);
}

// ---------------------------------------------------------------------------
// W -> fp16
// ---------------------------------------------------------------------------
__global__ void whalf_k(const float* __restrict__ W, __half* __restrict__ h, int n)
{
    int i = blockIdx.x * blockDim.x + threadIdx.x;
    if (i < n) h[i] = __float2half_rn(W[i]);
}

// ---------------------------------------------------------------------------
// GEMM1 (merged nb+x, fp16 single-pass): C[.,256] = sign(A[.,1024]) @ W1^T + b1.
// grid = (n-tiles=2, m-tiles=520): the two n-tiles of one m-tile have adjacent
// linear block ids -> co-resident -> second one's A reads hit L2.
// CTA tile 128x128, K-chunk 64, 8 warps, 2 CTAs/SM.
// SMEM: [A0 16K][A1 16K][B0 16K][B1 16K] = 64KB. cp.async 2-deep for B.
// ---------------------------------------------------------------------------
#define G1_SMEM (4 * 16384)

__global__ __launch_bounds__(256, 2)
void tc_gemm1_k(const float* __restrict__ Anb, const float* __restrict__ Ax,
                const __half* __restrict__ Wh, const float* __restrict__ bias,
                float* __restrict__ Cnb, float* __restrict__ Cx)
{
    extern __shared__ char smem[];
    const uint32_t sb = smem_u32(smem);
    const int K = Fn;

    const int tid = threadIdx.x;
    const int wid = tid >> 5, lane = tid & 31;
    const int by = blockIdx.y;
    const int n0 = blockIdx.x * 128;

    const float* Abase;  float* Cbase;  int m0;
    if (by < Mn / 128) { Abase = Anb; Cbase = Cnb; m0 = by * 128; }
    else               { Abase = Ax;  Cbase = Cx;  m0 = (by - Mn / 128) * 128; }

    const int mrow0 = (wid >> 1) * 32;
    const int ncol0 = (wid & 1) * 64;

    const int r  = tid >> 1;
    const int c0 = (tid & 1) * 32;
    const float* aSrc = Abase + (size_t)(m0 + r) * K + c0;
    const __half* hSrc = Wh + (size_t)(n0 + r) * K + c0;

    uint32_t sOff[4];
#pragma unroll
    for (int j = 0; j < 4; j++)
        sOff[j] = swz128((uint32_t)(r * 128 + (c0 + j * 8) * 2));

    float acc[2][8][4];
#pragma unroll
    for (int i = 0; i < 2; i++)
#pragma unroll
        for (int g = 0; g < 8; g++)
#pragma unroll
            for (int q = 0; q < 4; q++) acc[i][g][q] = 0.f;

    const int aRow[2] = { mrow0 + (lane & 15), mrow0 + 16 + (lane & 15) };
    const int aKof   = (lane >> 4) << 3;
    const int bRowBase = ncol0 + (lane & 7) + ((lane >> 4) << 3);
    const int bKof   = ((lane >> 3) & 1) << 3;

    // ---- prologue: 2-deep cp.async pipeline for B tiles ----
#pragma unroll
    for (int j = 0; j < 4; j++) cp16(sb + 32768 + sOff[j], hSrc + j * 8);
    CP_COMMIT();
#pragma unroll
    for (int j = 0; j < 4; j++) cp16(sb + 32768 + 16384 + sOff[j], hSrc + 64 + j * 8);
    CP_COMMIT();

    const int nCh = K / 64;   // 16
    for (int ch = 0; ch < nCh; ch++) {
        const int buf = ch & 1;
        const uint32_t aB = sb + buf * 16384;
        const uint32_t bB = sb + 32768 + buf * 16384;
        const int k0 = ch * 64;

        // A: LDG fp32 -> sign-pack fp16 -> swizzled STS
#pragma unroll
        for (int j = 0; j < 4; j++) {
            float4 f0 = *(const float4*)(aSrc + k0 + j * 8);
            float4 f1 = *(const float4*)(aSrc + k0 + j * 8 + 4);
            uint4 o;
            o.x = pack_sign_half2(f0.x, f0.y);
            o.y = pack_sign_half2(f0.z, f0.w);
            o.z = pack_sign_half2(f1.x, f1.y);
            o.w = pack_sign_half2(f1.z, f1.w);
            *(uint4*)(smem + buf * 16384 + sOff[j]) = o;
        }
        CP_WAIT1();
        __syncthreads();

#pragma unroll
        for (int ks = 0; ks < 4; ks++) {
            uint32_t af[2][4], bf_[4][4];
#pragma unroll
            for (int mi = 0; mi < 2; mi++)
                ldsm_x4(af[mi], aB + swz128((uint32_t)(aRow[mi] * 128 + (ks * 16 + aKof) * 2)));
#pragma unroll
            for (int q = 0; q < 4; q++)
                ldsm_x4(bf_[q], bB + swz128((uint32_t)((bRowBase + q * 16) * 128 +
                                                       (ks * 16 + bKof) * 2)));
#pragma unroll
            for (int mi = 0; mi < 2; mi++)
#pragma unroll
                for (int g = 0; g < 8; g++)
                    mma16816_f16(acc[mi][g], af[mi], &bf_[g >> 1][(g & 1) * 2]);
        }
        __syncthreads();

        if (ch + 2 < nCh) {
            const int k2 = (ch + 2) * 64;
#pragma unroll
            for (int j = 0; j < 4; j++) cp16(bB + sOff[j], hSrc + k2 + j * 8);
            CP_COMMIT();
        }
    }

    // ---- epilogue: bias add + fp32 store ----
#pragma unroll
    for (int mi = 0; mi < 2; mi++) {
        const int row = m0 + mrow0 + mi * 16 + (lane >> 2);
#pragma unroll
        for (int g = 0; g < 8; g++) {
            const int col = n0 + ncol0 + g * 8 + (lane & 3) * 2;
            const float b0 = bias[col], b1 = bias[col + 1];
            *(float2*)(Cbase + (size_t)row * H1n + col) =
                make_float2(acc[mi][g][0] + b0, acc[mi][g][1] + b1);
            *(float2*)(Cbase + (size_t)(row + 8) * H1n + col) =
                make_float2(acc[mi][g][2] + b0, acc[mi][g][3] + b1);
        }
    }
}

// ---------------------------------------------------------------------------
// GEMM2 (merged, fp16 single-pass): C[.,128] = BN_ReLU(A[.,256]) @ W2^T + b2.
// Whole W2 (fp16, 64KB) cached in SMEM once; A chunks single-buffered.
// SMEM: [A 16K][B 64K] = 80KB, 2 CTAs/SM.
// ---------------------------------------------------------------------------
#define G2_SMEM (16384 + 4 * 16384)

__global__ __launch_bounds__(256, 2)
void tc_gemm2_k(const float* __restrict__ Anb, const float* __restrict__ Ax,
                const __half* __restrict__ Wh, const float* __restrict__ bias,
                float* __restrict__ Cnb, float* __restrict__ Cx,
                const float* __restrict__ mb, const float* __restrict__ rb,
                const float* __restrict__ bn,
                const float* __restrict__ gptr, const float* __restrict__ beptr)
{
    extern __shared__ char smem[];
    const uint32_t sb = smem_u32(smem);
    const uint32_t aB  = sb;
    const uint32_t bB0 = sb + 16384;

    const int tid = threadIdx.x;
    const int wid = tid >> 5, lane = tid & 31;
    const int bx = blockIdx.x;

    const int r  = tid >> 1;
    const int c0 = (tid & 1) * 32;

    const float* Abase;  float* Cbase;  int m0;
    float rm, rr;
    if (bx < Mn / 128) {
        Abase = Anb; Cbase = Cnb; m0 = bx * 128;
        rm = mb[(m0 + r) / Nn]; rr = rb[(m0 + r) / Nn];
    } else {
        Abase = Ax; Cbase = Cx; m0 = (bx - Mn / 128) * 128;
        rm = bn[0]; rr = bn[1];
    }
    const float gg = *gptr, bb = *beptr;

    const int mrow0 = (wid >> 1) * 32;
    const int ncol0 = (wid & 1) * 64;

    const float* aSrc = Abase + (size_t)(m0 + r) * H1n + c0;
    const __half* hSrc = Wh + (size_t)r * H1n + c0;   // n-row = r (128 rows)

    uint32_t sOff[4];
#pragma unroll
    for (int j = 0; j < 4; j++)
        sOff[j] = swz128((uint32_t)(r * 128 + (c0 + j * 8) * 2));

    float acc[2][8][4];
#pragma unroll
    for (int i = 0; i < 2; i++)
#pragma unroll
        for (int g = 0; g < 8; g++)
#pragma unroll
            for (int q = 0; q < 4; q++) acc[i][g][q] = 0.f;

    const int aRow[2] = { mrow0 + (lane & 15), mrow0 + 16 + (lane & 15) };
    const int aKof   = (lane >> 4) << 3;
    const int bRowBase = ncol0 + (lane & 7) + ((lane >> 4) << 3);
    const int bKof   = ((lane >> 3) & 1) << 3;

    // ---- prologue: load ALL of W2 into SMEM (4 K-chunks x 16KB) ----
#pragma unroll
    for (int kc = 0; kc < 4; kc++)
#pragma unroll
        for (int j = 0; j < 4; j++)
            cp16(bB0 + kc * 16384 + sOff[j], hSrc + kc * 64 + j * 8);
    CP_COMMIT();

    for (int kc = 0; kc < 4; kc++) {
        const int k0 = kc * 64;
        // producer: BN-ReLU -> fp16 pack -> swizzled STS (single A buffer)
#pragma unroll
        for (int j = 0; j < 4; j++) {
            float4 f0 = *(const float4*)(aSrc + k0 + j * 8);
            float4 f1 = *(const float4*)(aSrc + k0 + j * 8 + 4);
            float v[8] = {f0.x, f0.y, f0.z, f0.w, f1.x, f1.y, f1.z, f1.w};
            float t[8];
#pragma unroll
            for (int e = 0; e < 8; e++)
                t[e] = fmaxf(gg * (v[e] - rm) * rr + bb, 0.f);
            uint4 o;
            o.x = pack_half2(t[0], t[1]);
            o.y = pack_half2(t[2], t[3]);
            o.z = pack_half2(t[4], t[5]);
            o.w = pack_half2(t[6], t[7]);
            *(uint4*)(smem + sOff[j]) = o;
        }
        if (kc == 0) CP_WAIT0();
        __syncthreads();

        const uint32_t bB = bB0 + kc * 16384;
#pragma unroll
        for (int ks = 0; ks < 4; ks++) {
            uint32_t af[2][4], bf_[4][4];
#pragma unroll
            for (int mi = 0; mi < 2; mi++)
                ldsm_x4(af[mi], aB + swz128((uint32_t)(aRow[mi] * 128 + (ks * 16 + aKof) * 2)));
#pragma unroll
            for (int q = 0; q < 4; q++)
                ldsm_x4(bf_[q], bB + swz128((uint32_t)((bRowBase + q * 16) * 128 +
                                                       (ks * 16 + bKof) * 2)));
#pragma unroll
            for (int mi = 0; mi < 2; mi++)
#pragma unroll
                for (int g = 0; g < 8; g++)
                    mma16816_f16(acc[mi][g], af[mi], &bf_[g >> 1][(g & 1) * 2]);
        }
        __syncthreads();
    }

    // ---- epilogue ----
#pragma unroll
    for (int mi = 0; mi < 2; mi++) {
        const int row = m0 + mrow0 + mi * 16 + (lane >> 2);
#pragma unroll
        for (int g = 0; g < 8; g++) {
            const int col = ncol0 + g * 8 + (lane & 3) * 2;
            const float b0 = bias[col], b1 = bias[col + 1];
            *(float2*)(Cbase + (size_t)row * H2n + col) =
                make_float2(acc[mi][g][0] + b0, acc[mi][g][1] + b1);
            *(float2*)(Cbase + (size_t)(row + 8) * H2n + col) =
                make_float2(acc[mi][g][2] + b0, acc[mi][g][3] + b1);
        }
    }
}

// ---------------------------------------------------------------------------
// Attention layer 1 (H=256). One block per graph node b, 256 threads.
// (R6 version: no smem tile cache — occupancy beats the DRAM re-read cost.)
// ---------------------------------------------------------------------------
__global__ void attn1_k(const float* __restrict__ nbh, const float* __restrict__ xh,
                        const float* __restrict__ a_self, const float* __restrict__ a_nb,
                        float* __restrict__ x1, float* __restrict__ mb,
                        float* __restrict__ rb, float* __restrict__ px,
                        float* __restrict__ pxq)
{
    const int b = blockIdx.x, tid = threadIdx.x;
    __shared__ float red[256];
    __shared__ float sc[64];

    const float* base = nbh + (size_t)b * Nn * H1n;

    red[tid] = xh[b * H1n + tid] * a_self[tid];
    __syncthreads();
    for (int s = 128; s > 0; s >>= 1) {
        if (tid < s) red[tid] += red[tid + s];
        __syncthreads();
    }
    const float sx = red[0];
    __syncthreads();

    const int w = tid >> 5, l = tid & 31;
#pragma unroll
    for (int nn = 0; nn < 8; nn++) {
        const int n = w * 8 + nn;
        const float* row = base + n * H1n;
        float acc = 0.f;
#pragma unroll
        for (int j = 0; j < 8; j++) acc += row[l + 32 * j] * a_nb[l + 32 * j];
#pragma unroll
        for (int o = 16; o > 0; o >>= 1) acc += __shfl_down_sync(0xffffffffu, acc, o);
        if (l == 0) sc[n] = sx + acc;
    }
    __syncthreads();

    if (w == 0) {
        float v0 = sc[l], v1 = sc[l + 32];
        v0 = v0 > 0.f ? v0 : ALPHA_LRELU * v0;
        v1 = v1 > 0.f ? v1 : ALPHA_LRELU * v1;
        float mx = fmaxf(v0, v1);
#pragma unroll
        for (int o = 16; o > 0; o >>= 1) mx = fmaxf(mx, __shfl_xor_sync(0xffffffffu, mx, o));
        float e0 = __expf(v0 - mx), e1 = __expf(v1 - mx);
        float s = e0 + e1;
#pragma unroll
        for (int o = 16; o > 0; o >>= 1) s += __shfl_xor_sync(0xffffffffu, s, o);
        const float inv = 1.f / s;
        sc[l] = e0 * inv; sc[l + 32] = e1 * inv;
    }
    __syncthreads();

    float acc = 0.f, sm = 0.f, sq = 0.f;
#pragma unroll 8
    for (int n = 0; n < Nn; n++) {
        const float v = base[n * H1n + tid];
        acc += sc[n] * v;
        sm += v;
        sq += v * v;
    }
    x1[b * H1n + tid] = acc;

    red[tid] = sm; __syncthreads();
    for (int s = 128; s > 0; s >>= 1) { if (tid < s) red[tid] += red[tid + s]; __syncthreads(); }
    const float S = red[0]; __syncthreads();
    red[tid] = sq; __syncthreads();
    for (int s = 128; s > 0; s >>= 1) { if (tid < s) red[tid] += red[tid + s]; __syncthreads(); }
    const float SQ = red[0]; __syncthreads();
    red[tid] = acc; __syncthreads();
    for (int s = 128; s > 0; s >>= 1) { if (tid < s) red[tid] += red[tid + s]; __syncthreads(); }
    const float SX = red[0]; __syncthreads();
    red[tid] = acc * acc; __syncthreads();
    for (int s = 128; s > 0; s >>= 1) { if (tid < s) red[tid] += red[tid + s]; __syncthreads(); }
    const float SXQ = red[0];

    if (tid == 0) {
        const float inv_cnt = 1.f / (float)(Nn * H1n);
        const float mean = S * inv_cnt;
        const float var  = SQ * inv_cnt - mean * mean;
        mb[b] = mean;
        rb[b] = rsqrtf(fmaxf(var, 0.f) + BN_EPS);
        px[b]  = SX;
        pxq[b] = SXQ;
    }
}

// ---------------------------------------------------------------------------
// Attention layer 2 (H=128). One block per node, 128 threads.
// ---------------------------------------------------------------------------
__global__ void attn2_k(const float* __restrict__ nbh, const float* __restrict__ xh,
                        const float* __restrict__ a_self, const float* __restrict__ a_nb,
                        float* __restrict__ x2, float* __restrict__ px,
                        float* __restrict__ pxq)
{
    const int b = blockIdx.x, tid = threadIdx.x;
    __shared__ float red[128];
    __shared__ float sc[64];

    const float* base = nbh + (size_t)b * Nn * H2n;

    red[tid] = xh[b * H2n + tid] * a_self[tid];
    __syncthreads();
    for (int s = 64; s > 0; s >>= 1) { if (tid < s) red[tid] += red[tid + s]; __syncthreads(); }
    const float sx = red[0];
    __syncthreads();

    const int w = tid >> 5, l = tid & 31;
#pragma unroll
    for (int nn = 0; nn < 16; nn++) {
        const int n = w * 16 + nn;
        const float* row = base + n * H2n;
        float acc = 0.f;
#pragma unroll
        for (int j = 0; j < 4; j++) acc += row[l + 32 * j] * a_nb[l + 32 * j];
#pragma unroll
        for (int o = 16; o > 0; o >>= 1) acc += __shfl_down_sync(0xffffffffu, acc, o);
        if (l == 0) sc[n] = sx + acc;
    }
    __syncthreads();

    if (w == 0) {
        float v0 = sc[l], v1 = sc[l + 32];
        v0 = v0 > 0.f ? v0 : ALPHA_LRELU * v0;
        v1 = v1 > 0.f ? v1 : ALPHA_LRELU * v1;
        float mx = fmaxf(v0, v1);
#pragma unroll
        for (int o = 16; o > 0; o >>= 1) mx = fmaxf(mx, __shfl_xor_sync(0xffffffffu, mx, o));
        float e0 = __expf(v0 - mx), e1 = __expf(v1 - mx);
        float s = e0 + e1;
#pragma unroll
        for (int o = 16; o > 0; o >>= 1) s += __shfl_xor_sync(0xffffffffu, s, o);
        const float inv = 1.f / s;
        sc[l] = e0 * inv; sc[l + 32] = e1 * inv;
    }
    __syncthreads();

    float acc = 0.f;
#pragma unroll 8
    for (int n = 0; n < Nn; n++) acc += sc[n] * base[n * H2n + tid];
    x2[b * H2n + tid] = acc;

    red[tid] = acc; __syncthreads();
    for (int s = 64; s > 0; s >>= 1) { if (tid < s) red[tid] += red[tid + s]; __syncthreads(); }
    const float SX = red[0]; __syncthreads();
    red[tid] = acc * acc; __syncthreads();
    for (int s = 64; s > 0; s >>= 1) { if (tid < s) red[tid] += red[tid + s]; __syncthreads(); }
    const float SXQ = red[0];

    if (tid == 0) { px[b] = SX; pxq[b] = SXQ; }
}

// ---------------------------------------------------------------------------
// Finalize global BN stats from per-block partials (1 block, 1024 threads).
// ---------------------------------------------------------------------------
__global__ void bnstats_k(const float* __restrict__ px, const float* __restrict__ pxq,
                          float* __restrict__ bn, float invcnt)
{
    __shared__ float r1[1024];
    __shared__ float r2[1024];
    const int t = threadIdx.x;
    r1[t] = px[t]; r2[t] = pxq[t];
    __syncthreads();
    for (int s = 512; s > 0; s >>= 1) {
        if (t < s) { r1[t] += r1[t + s]; r2[t] += r2[t + s]; }
        __syncthreads();
    }
    if (t == 0) {
        const float mean = r1[0] * invcnt;
        const float var  = r2[0] * invcnt - mean * mean;
        bn[0] = mean;
        bn[1] = rsqrtf(fmaxf(var, 0.f) + BN_EPS);
    }
}

// ---------------------------------------------------------------------------
// Final: BN-ReLU x2 + logits. One block per b, 128 threads.
// ---------------------------------------------------------------------------
__global__ void logits_k(const float* __restrict__ x2, const float* __restrict__ bn2,
                         const float* __restrict__ gptr, const float* __restrict__ beptr,
                         const float* __restrict__ Wl, const float* __restrict__ bl,
                         float* __restrict__ out)
{
    const int b = blockIdx.x, t = threadIdx.x;
    __shared__ float xn[H2n];
    const float m = bn2[0], r = bn2[1], g = gptr[0], be = beptr[0];
    float v = x2[b * H2n + t];
    xn[t] = fmaxf(g * (v - m) * r + be, 0.f);
    __syncthreads();

    const float* wr = Wl + t * H2n;
    float acc = bl[t];
#pragma unroll 8
    for (int h = 0; h < H2n; h++) acc += xn[h] * wr[h];
    out[b * NCn + t] = acc;
}

// ---------------------------------------------------------------------------
// Launch
// ---------------------------------------------------------------------------
extern "C" void kernel_launch(void* const* d_in, const int* in_sizes, int n_in,
                              void* d_out, int out_size)
{
    (void)in_sizes; (void)n_in; (void)out_size;
    const float* x   = (const float*)d_in[0];
    const float* nb  = (const float*)d_in[1];
    const float* W1  = (const float*)d_in[2];
    const float* b1  = (const float*)d_in[3];
    const float* a11 = (const float*)d_in[4];
    const float* a12 = (const float*)d_in[5];
    const float* g1  = (const float*)d_in[6];
    const float* be1 = (const float*)d_in[7];
    const float* W2  = (const float*)d_in[8];
    const float* b2  = (const float*)d_in[9];
    const float* a21 = (const float*)d_in[10];
    const float* a22 = (const float*)d_in[11];
    const float* g2  = (const float*)d_in[12];
    const float* be2 = (const float*)d_in[13];
    const float* Wl  = (const float*)d_in[14];
    const float* bl  = (const float*)d_in[15];
    float* out = (float*)d_out;

    float *nbh1, *xh1, *x1, *mb1, *rb1, *px1, *pxq1, *bn1;
    float *nbh2, *xh2, *x2, *px2, *pxq2, *bn2;
    __half *w1h, *w2h;
    cudaGetSymbolAddress((void**)&nbh1, g_nbh1);
    cudaGetSymbolAddress((void**)&xh1,  g_xh1);
    cudaGetSymbolAddress((void**)&x1,   g_x1);
    cudaGetSymbolAddress((void**)&mb1,  g_mb1);
    cudaGetSymbolAddress((void**)&rb1,  g_rb1);
    cudaGetSymbolAddress((void**)&px1,  g_px1);
    cudaGetSymbolAddress((void**)&pxq1, g_pxq1);
    cudaGetSymbolAddress((void**)&bn1,  g_bn1);
    cudaGetSymbolAddress((void**)&nbh2, g_nbh2);
    cudaGetSymbolAddress((void**)&xh2,  g_xh2);
    cudaGetSymbolAddress((void**)&x2,   g_x2);
    cudaGetSymbolAddress((void**)&px2,  g_px2);
    cudaGetSymbolAddress((void**)&pxq2, g_pxq2);
    cudaGetSymbolAddress((void**)&bn2,  g_bn2);
    cudaGetSymbolAddress((void**)&w1h,  g_w1h);
    cudaGetSymbolAddress((void**)&w2h,  g_w2h);

    cudaFuncSetAttribute(tc_gemm1_k, cudaFuncAttributeMaxDynamicSharedMemorySize, G1_SMEM);
    cudaFuncSetAttribute(tc_gemm2_k, cudaFuncAttributeMaxDynamicSharedMemorySize, G2_SMEM);

    // Weight conversions
    whalf_k<<<(H1n * Fn) / 1024, 1024>>>(W1, w1h, H1n * Fn);
    whalf_k<<<(H2n * H1n) / 1024, 1024>>>(W2, w2h, H2n * H1n);

    // Layer 1 GEMM (merged nb + x, fp16): grid (n-tiles, m-tiles) for L2 reuse
    tc_gemm1_k<<<dim3(H1n / 128, Mn / 128 + Bn / 128), 256, G1_SMEM>>>(
        nb, x, w1h, b1, nbh1, xh1);

    // Attention 1 + per-node neighbor BN stats + x1 partial stats
    attn1_k<<<Bn, 256>>>(nbh1, xh1, a11, a12, x1, mb1, rb1, px1, pxq1);
    bnstats_k<<<1, 1024>>>(px1, pxq1, bn1, 1.f / (float)(Bn * H1n));

    // Layer 2 GEMM (merged, fp16 single-pass, W2 resident in SMEM)
    tc_gemm2_k<<<Mn / 128 + Bn / 128, 256, G2_SMEM>>>(
        nbh1, x1, w2h, b2, nbh2, xh2, mb1, rb1, bn1, g1, be1);

    // Attention 2 + x2 partial stats
    attn2_k<<<Bn, 128>>>(nbh2, xh2, a21, a22, x2, px2, pxq2);
    bnstats_k<<<1, 1024>>>(px2, pxq2, bn2, 1.f / (float)(Bn * H2n));

    // BN-ReLU + classifier
    logits_k<<<Bn, 128>>>(x2, bn2, g2, be2, Wl, bl, out);
}